// round 8
// baseline (speedup 1.0000x reference)
#include <cuda_runtime.h>
#include <cstdint>
#include <cstddef>

#define NN 4096
#define MM 4096
#define DD 1024
// k = int(4096*4096*0.3) = 5033164 ; ascending 0-based rank = 16777216 - k
#define RANK_ASC 11744052u
#define NB 32          // DP column chunks
#define CW 128         // columns per chunk
#define PF 8           // sim prefetch ring depth (power of 2)
#define TBR 448        // traceback tile rows (smem < 48KB)

// ---------------- static device scratch (no allocations allowed) ----------------
__device__ float    g_z[(size_t)NN * DD];
__device__ float    g_x[(size_t)MM * DD];
__device__ float    g_sim[(size_t)NN * MM];
// decision bytes: g_dec[row*1024 + chunk*32 + lane]; bit s   = diag(col 4*lane+s)
//                                                    bit 4+s = up  (col 4*lane+s)
__device__ unsigned char g_dec[(size_t)NN * 1024];
__device__ float    g_bound[(size_t)(NN + 1) * NB];
__device__ unsigned g_hist[256];
__device__ unsigned g_sel[2];   // [0]=prefix key, [1]=remaining rank
__device__ unsigned g_ncand;
__device__ unsigned g_cand[(size_t)NN * MM];   // prefix-8 matchers (cannot overflow)
__device__ float    g_dropline;

// ---------------- helpers ----------------
__device__ __forceinline__ unsigned fkey(float f) {
    unsigned u = __float_as_uint(f);
    return (u & 0x80000000u) ? ~u : (u | 0x80000000u);
}

// ---------------- init (must reset all mutable state every replay) ----------------
__global__ void init_state() {
    int idx = blockIdx.x * blockDim.x + threadIdx.x;
    if (idx < 256) g_hist[idx] = 0u;
    if (idx == 0) { g_sel[0] = 0u; g_sel[1] = RANK_ASC; g_ncand = 0u; }
    int total = (NN + 1) * NB;
    for (int i = idx; i < total; i += gridDim.x * blockDim.x)
        g_bound[i] = 1.0f;   // sentinel: real D values are always <= 0
}

__global__ void fill_zero4(float4* __restrict__ out, size_t n4) {
    size_t stride = (size_t)gridDim.x * blockDim.x;
    float4 z; z.x = z.y = z.z = z.w = 0.f;
    for (size_t i = blockIdx.x * (size_t)blockDim.x + threadIdx.x; i < n4; i += stride)
        out[i] = z;
}

// ---------------- row normalize ----------------
__global__ void normalize_rows(const float* __restrict__ in, int which) {
    int row = blockIdx.x;
    int t = threadIdx.x;                 // 256 threads
    const float* p = in + (size_t)row * DD;
    float s = 0.f;
#pragma unroll
    for (int k = 0; k < 4; k++) { float v = p[t + k * 256]; s = fmaf(v, v, s); }
    __shared__ float red[256];
    red[t] = s; __syncthreads();
    for (int o = 128; o > 0; o >>= 1) { if (t < o) red[t] += red[t + o]; __syncthreads(); }
    float nrm = sqrtf(red[0]);
    float* q = (which == 0 ? g_z : g_x) + (size_t)row * DD;
#pragma unroll
    for (int k = 0; k < 4; k++) q[t + k * 256] = p[t + k * 256] / nrm;
}

// ---------------- f32 NT GEMM + fused pass-0 histogram epilogue ----------------
// Accumulation order identical to scalar version => bitwise-identical sim.
__global__ void __launch_bounds__(256) gemm_nt() {
    __shared__ __align__(16) float As[2][16][132];
    __shared__ __align__(16) float Bs[2][16][132];
    __shared__ unsigned eh[8][256];
    int tid = threadIdx.x;
    int ty = tid >> 4;   // 0..15
    int tx = tid & 15;   // 0..15
    int wid = tid >> 5;
    int bi = blockIdx.y * 128;
    int bj = blockIdx.x * 128;

    int arow0 = tid >> 2;            // 0..63
    int a4 = (tid & 3) * 4;          // 0,4,8,12

    // acc2[rp][c] packs rows (ty*8+2rp, ty*8+2rp+1) at column tx*8+c
    unsigned long long acc2[4][8];
#pragma unroll
    for (int rp = 0; rp < 4; rp++)
#pragma unroll
        for (int c = 0; c < 8; c++) acc2[rp][c] = 0ull;

    for (int k = tid; k < 8 * 256; k += 256) ((unsigned*)eh)[k] = 0u;
    {
        float4 va0 = *reinterpret_cast<const float4*>(&g_z[(size_t)(bi + arow0) * DD + a4]);
        float4 va1 = *reinterpret_cast<const float4*>(&g_z[(size_t)(bi + arow0 + 64) * DD + a4]);
        float4 vb0 = *reinterpret_cast<const float4*>(&g_x[(size_t)(bj + arow0) * DD + a4]);
        float4 vb1 = *reinterpret_cast<const float4*>(&g_x[(size_t)(bj + arow0 + 64) * DD + a4]);
        As[0][a4 + 0][arow0] = va0.x; As[0][a4 + 1][arow0] = va0.y;
        As[0][a4 + 2][arow0] = va0.z; As[0][a4 + 3][arow0] = va0.w;
        As[0][a4 + 0][arow0 + 64] = va1.x; As[0][a4 + 1][arow0 + 64] = va1.y;
        As[0][a4 + 2][arow0 + 64] = va1.z; As[0][a4 + 3][arow0 + 64] = va1.w;
        Bs[0][a4 + 0][arow0] = vb0.x; Bs[0][a4 + 1][arow0] = vb0.y;
        Bs[0][a4 + 2][arow0] = vb0.z; Bs[0][a4 + 3][arow0] = vb0.w;
        Bs[0][a4 + 0][arow0 + 64] = vb1.x; Bs[0][a4 + 1][arow0 + 64] = vb1.y;
        Bs[0][a4 + 2][arow0 + 64] = vb1.z; Bs[0][a4 + 3][arow0 + 64] = vb1.w;
    }
    __syncthreads();

    int s = 0;
    for (int k0 = 0; k0 < DD; k0 += 16, s ^= 1) {
        float4 va0, va1, vb0, vb1;
        bool more = (k0 + 16 < DD);
        if (more) {
            int kn = k0 + 16;
            va0 = *reinterpret_cast<const float4*>(&g_z[(size_t)(bi + arow0) * DD + kn + a4]);
            va1 = *reinterpret_cast<const float4*>(&g_z[(size_t)(bi + arow0 + 64) * DD + kn + a4]);
            vb0 = *reinterpret_cast<const float4*>(&g_x[(size_t)(bj + arow0) * DD + kn + a4]);
            vb1 = *reinterpret_cast<const float4*>(&g_x[(size_t)(bj + arow0 + 64) * DD + kn + a4]);
        }
#pragma unroll
        for (int kk = 0; kk < 16; kk++) {
            const ulonglong2* ap2 = reinterpret_cast<const ulonglong2*>(&As[s][kk][ty * 8]);
            ulonglong2 aa = ap2[0], ab = ap2[1];
            unsigned long long a2[4];
            a2[0] = aa.x; a2[1] = aa.y; a2[2] = ab.x; a2[3] = ab.y;
            const float4* bp = reinterpret_cast<const float4*>(&Bs[s][kk][tx * 8]);
            float4 b0 = bp[0], b1 = bp[1];
            float bbv[8];
            bbv[0] = b0.x; bbv[1] = b0.y; bbv[2] = b0.z; bbv[3] = b0.w;
            bbv[4] = b1.x; bbv[5] = b1.y; bbv[6] = b1.z; bbv[7] = b1.w;
            unsigned long long b2[8];
#pragma unroll
            for (int c = 0; c < 8; c++)
                asm("mov.b64 %0, {%1, %1};" : "=l"(b2[c]) : "r"(__float_as_uint(bbv[c])));
#pragma unroll
            for (int c = 0; c < 8; c++)
#pragma unroll
                for (int rp = 0; rp < 4; rp++)
                    asm("fma.rn.f32x2 %0, %1, %2, %0;"
                        : "+l"(acc2[rp][c]) : "l"(a2[rp]), "l"(b2[c]));
        }
        __syncthreads();
        if (more) {
            int d = s ^ 1;
            As[d][a4 + 0][arow0] = va0.x; As[d][a4 + 1][arow0] = va0.y;
            As[d][a4 + 2][arow0] = va0.z; As[d][a4 + 3][arow0] = va0.w;
            As[d][a4 + 0][arow0 + 64] = va1.x; As[d][a4 + 1][arow0 + 64] = va1.y;
            As[d][a4 + 2][arow0 + 64] = va1.z; As[d][a4 + 3][arow0 + 64] = va1.w;
            Bs[d][a4 + 0][arow0] = vb0.x; Bs[d][a4 + 1][arow0] = vb0.y;
            Bs[d][a4 + 2][arow0] = vb0.z; Bs[d][a4 + 3][arow0] = vb0.w;
            Bs[d][a4 + 0][arow0 + 64] = vb1.x; Bs[d][a4 + 1][arow0 + 64] = vb1.y;
            Bs[d][a4 + 2][arow0 + 64] = vb1.z; Bs[d][a4 + 3][arow0 + 64] = vb1.w;
            __syncthreads();
        }
    }
#pragma unroll
    for (int rp = 0; rp < 4; rp++) {
        float lo[8], hi[8];
#pragma unroll
        for (int c = 0; c < 8; c++) {
            lo[c] = __uint_as_float((unsigned)(acc2[rp][c] & 0xffffffffull));
            hi[c] = __uint_as_float((unsigned)(acc2[rp][c] >> 32));
        }
        float* dst0 = &g_sim[(size_t)(bi + ty * 8 + 2 * rp) * MM + (bj + tx * 8)];
        float* dst1 = &g_sim[(size_t)(bi + ty * 8 + 2 * rp + 1) * MM + (bj + tx * 8)];
        float4 o;
        o.x = lo[0]; o.y = lo[1]; o.z = lo[2]; o.w = lo[3];
        *reinterpret_cast<float4*>(dst0) = o;
        o.x = lo[4]; o.y = lo[5]; o.z = lo[6]; o.w = lo[7];
        *reinterpret_cast<float4*>(dst0 + 4) = o;
        o.x = hi[0]; o.y = hi[1]; o.z = hi[2]; o.w = hi[3];
        *reinterpret_cast<float4*>(dst1) = o;
        o.x = hi[4]; o.y = hi[5]; o.z = hi[6]; o.w = hi[7];
        *reinterpret_cast<float4*>(dst1 + 4) = o;
        // fused pass-0 histogram (top 8 bits of fkey)
#pragma unroll
        for (int c = 0; c < 8; c++) {
            atomicAdd(&eh[wid][fkey(lo[c]) >> 24], 1u);
            atomicAdd(&eh[wid][fkey(hi[c]) >> 24], 1u);
        }
    }
    __syncthreads();
    unsigned tot = 0;
#pragma unroll
    for (int w = 0; w < 8; w++) tot += eh[w][tid];
    if (tot) atomicAdd(&g_hist[tid], tot);
}

// ---------------- pass 1: histogram bits 16-23 of prefix-8 matchers + compaction ----------------
__global__ void hist_compact16() {
    __shared__ unsigned sh[8][256];
    int t = threadIdx.x;
    int wid = t >> 5, lane = t & 31;
    for (int k = t; k < 8 * 256; k += 256) ((unsigned*)sh)[k] = 0u;
    __syncthreads();
    unsigned prefix = g_sel[0];
    size_t stride = (size_t)gridDim.x * blockDim.x;
    size_t total = (size_t)NN * MM;   // divisible by stride -> convergent loop
    for (size_t i = blockIdx.x * (size_t)blockDim.x + threadIdx.x; i < total; i += stride) {
        unsigned u = fkey(g_sim[i]);
        bool ok = (u >> 24) == (prefix >> 24);
        unsigned ball = __ballot_sync(0xffffffffu, ok);
        if (ball) {
            unsigned base = 0;
            if (lane == 0) base = atomicAdd(&g_ncand, (unsigned)__popc(ball));
            base = __shfl_sync(0xffffffffu, base, 0);
            if (ok) {
                int pos = __popc(ball & ((1u << lane) - 1u));
                g_cand[base + pos] = u;
                atomicAdd(&sh[wid][(u >> 16) & 255u], 1u);
            }
        }
    }
    __syncthreads();
    unsigned tot = 0;
#pragma unroll
    for (int w = 0; w < 8; w++) tot += sh[w][t];
    if (tot) atomicAdd(&g_hist[t], tot);
}

// ---------------- passes 2-3: histogram over candidates ----------------
__global__ void hist_cand(int shift) {
    __shared__ unsigned sh[8][256];
    int t = threadIdx.x;
    int wid = t >> 5;
    for (int k = t; k < 8 * 256; k += 256) ((unsigned*)sh)[k] = 0u;
    __syncthreads();
    unsigned prefix = g_sel[0];
    int above = shift + 8;
    unsigned n = g_ncand;
    unsigned stride = gridDim.x * blockDim.x;
    for (unsigned i = blockIdx.x * blockDim.x + threadIdx.x; i < n; i += stride) {
        unsigned u = g_cand[i];
        if ((u >> above) == (prefix >> above)) atomicAdd(&sh[wid][(u >> shift) & 255u], 1u);
    }
    __syncthreads();
    unsigned tot = 0;
#pragma unroll
    for (int w = 0; w < 8; w++) tot += sh[w][t];
    if (tot) atomicAdd(&g_hist[t], tot);
}

__global__ void select_pass(int shift, int last) {
    __shared__ unsigned cnt[256];
    int t = threadIdx.x;
    cnt[t] = g_hist[t];
    g_hist[t] = 0u;   // reset for the next pass
    __syncthreads();
    if (t == 0) {
        unsigned rank = g_sel[1], cum = 0; int bin = 255;
        for (int b = 0; b < 256; b++) {
            unsigned c = cnt[b];
            if (cum + c > rank) { bin = b; break; }
            cum += c;
        }
        g_sel[0] |= ((unsigned)bin) << shift;
        g_sel[1] = rank - cum;
        if (last) {
            unsigned u = g_sel[0];
            unsigned bits = (u & 0x80000000u) ? (u & 0x7FFFFFFFu) : ~u;
            g_dropline = __uint_as_float(bits);
        }
    }
}

// ---------------- NW DP wavefront (rows parameterized so a probe can run 1/4) ----------------
__global__ void __launch_bounds__(32, 1) dp_kernel(int rows) {
    const int b = blockIdx.x;
    const int lane = threadIdx.x;          // 32 lanes, lane handles cols c0+4*lane .. +3
    const int c0 = b * CW;
    const float dropline = g_dropline;

    __shared__ __align__(16) float s_sim[PF][CW];   // 4KB ring, each lane owns its 16B slot

    const float* gsim = g_sim + c0 + 4 * lane;
    unsigned sslot = (unsigned)__cvta_generic_to_shared(&s_sim[0][4 * lane]);
    const unsigned sstride = CW * 4;   // bytes per stage

    // prologue: issue rows 0..PF-2
#pragma unroll
    for (int r = 0; r < PF - 1; ++r) {
        asm volatile("cp.async.cg.shared.global [%0], [%1], 16;\n"
                     :: "r"(sslot + r * sstride), "l"(gsim + (size_t)r * MM));
        asm volatile("cp.async.commit_group;\n");
    }

    float prev0 = 0.f, prev1 = 0.f, prev2 = 0.f, prev3 = 0.f;  // D[i-1] at this lane's 4 cols
    float prevBound = 0.f;                                      // D[i-1][c0]
    unsigned char* decp = g_dec + b * 32 + lane;

    for (int i = 1; i <= rows; ++i) {
        int r = i - 1;
        int rn = r + PF - 1;
        if (rn < rows)
            asm volatile("cp.async.cg.shared.global [%0], [%1], 16;\n"
                         :: "r"(sslot + (rn & (PF - 1)) * sstride), "l"(gsim + (size_t)rn * MM));
        asm volatile("cp.async.commit_group;\n");
        asm volatile("cp.async.wait_group 7;\n");
        float4 simCur = *reinterpret_cast<const float4*>(&s_sim[r & (PF - 1)][4 * lane]);

        volatile float* pb = (volatile float*)&g_bound[(size_t)i * NB + b];
        float incoming = (b == 0) ? 0.f : *pb;   // issue early; verify later

        float cc0 = dropline - simCur.x;
        float cc1 = dropline - simCur.y;
        float cc2 = dropline - simCur.z;
        float cc3 = dropline - simCur.w;

        float edge = __shfl_up_sync(0xffffffffu, prev3, 1);   // D[i-1][c0+4*lane]
        float left0 = (lane == 0) ? prevBound : edge;

        float d0 = left0 + cc0;
        float d1 = prev0 + cc1;
        float d2 = prev1 + cc2;
        float d3 = prev2 + cc3;
        float n0 = fminf(d0, prev0);
        float n1 = fminf(d1, prev1);
        float n2 = fminf(d2, prev2);
        float n3 = fminf(d3, prev3);
        float p0 = n0;
        float p1 = fminf(p0, n1);
        float p2 = fminf(p1, n2);
        float p3 = fminf(p2, n3);

        // warp inclusive min-scan of lane totals
        float S = p3;
#pragma unroll
        for (int o = 1; o < 32; o <<= 1) {
            float v = __shfl_up_sync(0xffffffffu, S, o);
            if (lane >= o) S = fminf(S, v);
        }
        float E = __shfl_up_sync(0xffffffffu, S, 1);   // exclusive prefix (lanes > 0)

        if (b != 0) { while (incoming > 0.5f) incoming = *pb; }

        float base = (lane == 0) ? incoming : fminf(incoming, E);
        float D0 = fminf(base, p0);
        float D1 = fminf(base, p1);
        float D2 = fminf(base, p2);
        float D3 = fminf(base, p3);

        // publish right boundary ASAP (lane 31's D3 == min(incoming, S_31))
        if (lane == 31 && b < NB - 1) {
            volatile float* q = (volatile float*)&g_bound[(size_t)i * NB + (b + 1)];
            *q = D3;
        }

        // pack decisions into one byte per lane (diag nibble low, up nibble high)
        bool df0 = (D0 == d0); bool uf0 = (!df0) && (D0 == prev0);
        bool df1 = (D1 == d1); bool uf1 = (!df1) && (D1 == prev1);
        bool df2 = (D2 == d2); bool uf2 = (!df2) && (D2 == prev2);
        bool df3 = (D3 == d3); bool uf3 = (!df3) && (D3 == prev3);
        unsigned byte = (df0 ? 1u : 0u) | (df1 ? 2u : 0u) | (df2 ? 4u : 0u) | (df3 ? 8u : 0u)
                      | (uf0 ? 16u : 0u) | (uf1 ? 32u : 0u) | (uf2 ? 64u : 0u) | (uf3 ? 128u : 0u);
        decp[(size_t)r * 1024] = (unsigned char)byte;

        prev0 = D0; prev1 = D1; prev2 = D2; prev3 = D3;
        prevBound = incoming;
    }
}

// ---------------- traceback: 448-row tiles, u64 nibble repack, left-run skipping ----------------
__device__ __forceinline__ unsigned nib_compact(unsigned long long x) {
    x &= 0x0F0F0F0F0F0F0F0Full;
    x = (x | (x >> 4))  & 0x00FF00FF00FF00FFull;
    x = (x | (x >> 8))  & 0x0000FFFF0000FFFFull;
    x = (x | (x >> 16));
    return (unsigned)x;
}

__global__ void traceback(float* __restrict__ out) {
    __shared__ uint2    s_du[TBR * 8];
    __shared__ unsigned s_c[TBR * 8];
    __shared__ int s_ij[2];
    int t = threadIdx.x;    // 256 threads
    int i = NN, j = MM;
    while (i > 0 && j > 0) {
        int ilo = (i - (TBR - 1) > 1) ? (i - (TBR - 1)) : 1;
        int jbhi = (j - 1) >> 7;                       // 128-col strip of current jj
        int jblo = (jbhi - 1 > 0) ? (jbhi - 1) : 0;    // stage 2 strips
        int rows = i - ilo + 1;
        for (int idx = t; idx < rows * 8; idx += 256) {
            int r = idx >> 3, wq = idx & 7;            // natural word 0..7 across 2 strips
            int strip = jblo + (wq >> 2), w4 = wq & 3;
            size_t boff = (size_t)(ilo - 1 + r) * 1024 + (size_t)strip * 32 + (size_t)w4 * 8;
            unsigned long long B = *reinterpret_cast<const unsigned long long*>(&g_dec[boff]);
            unsigned dw = nib_compact(B);
            unsigned uw = nib_compact(B >> 4);
            s_du[r * 8 + wq] = make_uint2(dw, uw);
            s_c[r * 8 + wq] = dw | uw;
        }
        __syncthreads();
        if (t == 0) {
            int jlo = jblo * 128 + 1;                  // smallest j inside the staged strips
            while (i >= ilo && j >= jlo) {
                int jj = j - 1;
                int r = i - ilo;
                int w = (jj >> 5) - jblo * 4;          // 0..7
                int bit = jj & 31;
                uint2 du = s_du[r * 8 + w];
                if ((du.x >> bit) & 1u) {
                    out[(size_t)(i - 1) * MM + jj] = 1.0f; --i; --j;
                } else if ((du.y >> bit) & 1u) {
                    --i;
                } else {
                    // left-run: skip to the nearest lower set bit of (diag|up)
                    unsigned m = s_c[r * 8 + w] & ((bit == 0) ? 0u : ((1u << bit) - 1u));
                    for (;;) {
                        if (m) { int nb = 31 - __clz(m); j = (jblo * 4 + w) * 32 + nb + 1; break; }
                        if (w == 0) { j = jlo - 1; break; }   // exits staged strips (or j==0)
                        --w;
                        m = s_c[r * 8 + w];
                    }
                }
            }
            s_ij[0] = i; s_ij[1] = j;
        }
        __syncthreads();
        i = s_ij[0]; j = s_ij[1];
        __syncthreads();
        // i==0 or j==0 => only zero-cost up/left moves remain, no more writes
    }
}

// ---------------- launch ----------------
extern "C" void kernel_launch(void* const* d_in, const int* in_sizes, int n_in,
                              void* d_out, int out_size) {
    (void)in_sizes; (void)n_in; (void)out_size;
    const float* text  = (const float*)d_in[2];
    const float* event = (const float*)d_in[3];
    float* out = (float*)d_out;

    // Launch #4 = dp probe (1024 rows) -> ncu (-s 5 -c 1 + 2 harness launches) profiles it.
    // Timing is data-independent; writes only g_dec (overwritten) and g_bound (re-init below).
    init_state<<<256, 256>>>();
    normalize_rows<<<NN, 256>>>(text, 0);
    normalize_rows<<<MM, 256>>>(event, 1);
    dp_kernel<<<NB, 32>>>(1024);          // PROBE
    init_state<<<256, 256>>>();           // reset g_bound/g_hist/g_sel/g_ncand
    gemm_nt<<<dim3(32, 32), 256>>>();     // includes fused pass-0 histogram
    select_pass<<<1, 256>>>(24, 0);
    hist_compact16<<<2048, 256>>>();
    select_pass<<<1, 256>>>(16, 0);
    hist_cand<<<256, 256>>>(8);
    select_pass<<<1, 256>>>(8, 0);
    hist_cand<<<256, 256>>>(0);
    select_pass<<<1, 256>>>(0, 1);
    fill_zero4<<<2048, 256>>>((float4*)out, (size_t)NN * MM / 4);
    dp_kernel<<<NB, 32>>>(NN);            // real DP
    traceback<<<1, 256>>>(out);
}

// round 9
// speedup vs baseline: 1.2905x; 1.2905x over previous
#include <cuda_runtime.h>
#include <cstdint>
#include <cstddef>

#define NN 4096
#define MM 4096
#define DD 1024
// k = int(4096*4096*0.3) = 5033164 ; ascending 0-based rank = 16777216 - k
#define RANK_ASC 11744052u
#define NB 32          // DP column chunks
#define CW 128         // columns per chunk
#define TBR 448        // traceback tile rows

// ---------------- static device scratch (no allocations allowed) ----------------
__device__ float    g_z[(size_t)NN * DD];
__device__ float    g_x[(size_t)MM * DD];
__device__ float    g_sim[(size_t)NN * MM];
// decision bytes, coalesced per block: g_dec[block*NN*32 + row*32 + lane]
//   bit s = diag(col 4*lane+s), bit 4+s = up(col 4*lane+s)   (cols local to block strip)
__device__ unsigned char g_dec[(size_t)NN * 1024];
__device__ float    g_bound[(size_t)(NN + 1) * NB];
__device__ unsigned g_hist[256];
__device__ unsigned g_sel[2];   // [0]=prefix key, [1]=remaining rank
__device__ float    g_dropline;

// ---------------- helpers ----------------
__device__ __forceinline__ unsigned fkey(float f) {
    unsigned u = __float_as_uint(f);
    return (u & 0x80000000u) ? ~u : (u | 0x80000000u);
}

// ---------------- init (must reset all mutable state every replay) ----------------
__global__ void init_state() {
    int idx = blockIdx.x * blockDim.x + threadIdx.x;
    if (idx < 256) g_hist[idx] = 0u;
    if (idx == 0) { g_sel[0] = 0u; g_sel[1] = RANK_ASC; }
    int total = (NN + 1) * NB;
    for (int i = idx; i < total; i += gridDim.x * blockDim.x)
        g_bound[i] = 1.0f;   // sentinel: real D values are always <= 0
}

__global__ void fill_zero4(float4* __restrict__ out, size_t n4) {
    size_t stride = (size_t)gridDim.x * blockDim.x;
    float4 z; z.x = z.y = z.z = z.w = 0.f;
    for (size_t i = blockIdx.x * (size_t)blockDim.x + threadIdx.x; i < n4; i += stride)
        out[i] = z;
}

// ---------------- row normalize ----------------
__global__ void normalize_rows(const float* __restrict__ in, int which) {
    int row = blockIdx.x;
    int t = threadIdx.x;                 // 256 threads
    const float* p = in + (size_t)row * DD;
    float s = 0.f;
#pragma unroll
    for (int k = 0; k < 4; k++) { float v = p[t + k * 256]; s = fmaf(v, v, s); }
    __shared__ float red[256];
    red[t] = s; __syncthreads();
    for (int o = 128; o > 0; o >>= 1) { if (t < o) red[t] += red[t + o]; __syncthreads(); }
    float nrm = sqrtf(red[0]);
    float* q = (which == 0 ? g_z : g_x) + (size_t)row * DD;
#pragma unroll
    for (int k = 0; k < 4; k++) q[t + k * 256] = p[t + k * 256] / nrm;
}

// ---------------- f32 NT GEMM, double-buffered smem, f32x2 packed FMA ----------------
// Accumulation order identical to scalar version => bitwise-identical sim.
__global__ void __launch_bounds__(256) gemm_nt() {
    __shared__ __align__(16) float As[2][16][132];
    __shared__ __align__(16) float Bs[2][16][132];
    int tid = threadIdx.x;
    int ty = tid >> 4;   // 0..15
    int tx = tid & 15;   // 0..15
    int bi = blockIdx.y * 128;
    int bj = blockIdx.x * 128;

    int arow0 = tid >> 2;            // 0..63
    int a4 = (tid & 3) * 4;          // 0,4,8,12

    unsigned long long acc2[4][8];
#pragma unroll
    for (int rp = 0; rp < 4; rp++)
#pragma unroll
        for (int c = 0; c < 8; c++) acc2[rp][c] = 0ull;

    {
        float4 va0 = *reinterpret_cast<const float4*>(&g_z[(size_t)(bi + arow0) * DD + a4]);
        float4 va1 = *reinterpret_cast<const float4*>(&g_z[(size_t)(bi + arow0 + 64) * DD + a4]);
        float4 vb0 = *reinterpret_cast<const float4*>(&g_x[(size_t)(bj + arow0) * DD + a4]);
        float4 vb1 = *reinterpret_cast<const float4*>(&g_x[(size_t)(bj + arow0 + 64) * DD + a4]);
        As[0][a4 + 0][arow0] = va0.x; As[0][a4 + 1][arow0] = va0.y;
        As[0][a4 + 2][arow0] = va0.z; As[0][a4 + 3][arow0] = va0.w;
        As[0][a4 + 0][arow0 + 64] = va1.x; As[0][a4 + 1][arow0 + 64] = va1.y;
        As[0][a4 + 2][arow0 + 64] = va1.z; As[0][a4 + 3][arow0 + 64] = va1.w;
        Bs[0][a4 + 0][arow0] = vb0.x; Bs[0][a4 + 1][arow0] = vb0.y;
        Bs[0][a4 + 2][arow0] = vb0.z; Bs[0][a4 + 3][arow0] = vb0.w;
        Bs[0][a4 + 0][arow0 + 64] = vb1.x; Bs[0][a4 + 1][arow0 + 64] = vb1.y;
        Bs[0][a4 + 2][arow0 + 64] = vb1.z; Bs[0][a4 + 3][arow0 + 64] = vb1.w;
    }
    __syncthreads();

    int s = 0;
    for (int k0 = 0; k0 < DD; k0 += 16, s ^= 1) {
        float4 va0, va1, vb0, vb1;
        bool more = (k0 + 16 < DD);
        if (more) {
            int kn = k0 + 16;
            va0 = *reinterpret_cast<const float4*>(&g_z[(size_t)(bi + arow0) * DD + kn + a4]);
            va1 = *reinterpret_cast<const float4*>(&g_z[(size_t)(bi + arow0 + 64) * DD + kn + a4]);
            vb0 = *reinterpret_cast<const float4*>(&g_x[(size_t)(bj + arow0) * DD + kn + a4]);
            vb1 = *reinterpret_cast<const float4*>(&g_x[(size_t)(bj + arow0 + 64) * DD + kn + a4]);
        }
#pragma unroll
        for (int kk = 0; kk < 16; kk++) {
            const ulonglong2* ap2 = reinterpret_cast<const ulonglong2*>(&As[s][kk][ty * 8]);
            ulonglong2 aa = ap2[0], ab = ap2[1];
            unsigned long long a2[4];
            a2[0] = aa.x; a2[1] = aa.y; a2[2] = ab.x; a2[3] = ab.y;
            const float4* bp = reinterpret_cast<const float4*>(&Bs[s][kk][tx * 8]);
            float4 b0 = bp[0], b1 = bp[1];
            float bbv[8];
            bbv[0] = b0.x; bbv[1] = b0.y; bbv[2] = b0.z; bbv[3] = b0.w;
            bbv[4] = b1.x; bbv[5] = b1.y; bbv[6] = b1.z; bbv[7] = b1.w;
            unsigned long long b2[8];
#pragma unroll
            for (int c = 0; c < 8; c++)
                asm("mov.b64 %0, {%1, %1};" : "=l"(b2[c]) : "r"(__float_as_uint(bbv[c])));
#pragma unroll
            for (int c = 0; c < 8; c++)
#pragma unroll
                for (int rp = 0; rp < 4; rp++)
                    asm("fma.rn.f32x2 %0, %1, %2, %0;"
                        : "+l"(acc2[rp][c]) : "l"(a2[rp]), "l"(b2[c]));
        }
        __syncthreads();
        if (more) {
            int d = s ^ 1;
            As[d][a4 + 0][arow0] = va0.x; As[d][a4 + 1][arow0] = va0.y;
            As[d][a4 + 2][arow0] = va0.z; As[d][a4 + 3][arow0] = va0.w;
            As[d][a4 + 0][arow0 + 64] = va1.x; As[d][a4 + 1][arow0 + 64] = va1.y;
            As[d][a4 + 2][arow0 + 64] = va1.z; As[d][a4 + 3][arow0 + 64] = va1.w;
            Bs[d][a4 + 0][arow0] = vb0.x; Bs[d][a4 + 1][arow0] = vb0.y;
            Bs[d][a4 + 2][arow0] = vb0.z; Bs[d][a4 + 3][arow0] = vb0.w;
            Bs[d][a4 + 0][arow0 + 64] = vb1.x; Bs[d][a4 + 1][arow0 + 64] = vb1.y;
            Bs[d][a4 + 2][arow0 + 64] = vb1.z; Bs[d][a4 + 3][arow0 + 64] = vb1.w;
            __syncthreads();
        }
    }
#pragma unroll
    for (int rp = 0; rp < 4; rp++) {
        float lo[8], hi[8];
#pragma unroll
        for (int c = 0; c < 8; c++) {
            lo[c] = __uint_as_float((unsigned)(acc2[rp][c] & 0xffffffffull));
            hi[c] = __uint_as_float((unsigned)(acc2[rp][c] >> 32));
        }
        float* dst0 = &g_sim[(size_t)(bi + ty * 8 + 2 * rp) * MM + (bj + tx * 8)];
        float* dst1 = &g_sim[(size_t)(bi + ty * 8 + 2 * rp + 1) * MM + (bj + tx * 8)];
        float4 o;
        o.x = lo[0]; o.y = lo[1]; o.z = lo[2]; o.w = lo[3];
        *reinterpret_cast<float4*>(dst0) = o;
        o.x = lo[4]; o.y = lo[5]; o.z = lo[6]; o.w = lo[7];
        *reinterpret_cast<float4*>(dst0 + 4) = o;
        o.x = hi[0]; o.y = hi[1]; o.z = hi[2]; o.w = hi[3];
        *reinterpret_cast<float4*>(dst1) = o;
        o.x = hi[4]; o.y = hi[5]; o.z = hi[6]; o.w = hi[7];
        *reinterpret_cast<float4*>(dst1 + 4) = o;
    }
}

// ---------------- exact radix select (R7 version: privatized per-warp hists) ----------------
__global__ void hist_pass(int shift) {
    __shared__ unsigned sh[8][256];
    int t = threadIdx.x;
    int wid = t >> 5;
    for (int k = t; k < 8 * 256; k += 256) ((unsigned*)sh)[k] = 0u;
    __syncthreads();
    unsigned prefix = g_sel[0];
    int above = shift + 8;
    size_t stride = (size_t)gridDim.x * blockDim.x;
    size_t total = (size_t)NN * MM;
    for (size_t i = blockIdx.x * (size_t)blockDim.x + threadIdx.x; i < total; i += stride) {
        unsigned u = fkey(g_sim[i]);
        bool ok = (above >= 32) || ((u >> above) == (prefix >> above));
        if (ok) atomicAdd(&sh[wid][(u >> shift) & 255u], 1u);
    }
    __syncthreads();
    unsigned tot = 0;
#pragma unroll
    for (int wq = 0; wq < 8; wq++) tot += sh[wq][t];
    if (tot) atomicAdd(&g_hist[t], tot);
}

__global__ void select_pass(int shift, int last) {
    __shared__ unsigned cnt[256];
    int t = threadIdx.x;
    cnt[t] = g_hist[t];
    g_hist[t] = 0u;   // reset for the next pass
    __syncthreads();
    if (t == 0) {
        unsigned rank = g_sel[1], cum = 0; int bin = 255;
        for (int b = 0; b < 256; b++) {
            unsigned c = cnt[b];
            if (cum + c > rank) { bin = b; break; }
            cum += c;
        }
        g_sel[0] |= ((unsigned)bin) << shift;
        g_sel[1] = rank - cum;
        if (last) {
            unsigned u = g_sel[0];
            unsigned bits = (u & 0x80000000u) ? (u & 0x7FFFFFFFu) : ~u;
            g_dropline = __uint_as_float(bits);
        }
    }
}

// ---------------- NW DP wavefront: base-carry (no edge shfl), coalesced decisions,
// ---------------- distance-2 register prefetch, per-row volatile handoff ----------------
__device__ __forceinline__ void dp_row(
    int b, int lane, int i, float dropline, float4 simCur,
    float& prev0, float& prev1, float& prev2, float& prev3,
    float& base, unsigned char* decp)
{
    volatile float* pb = (volatile float*)&g_bound[(size_t)i * NB + b];
    float incoming = (b == 0) ? 0.f : *pb;   // issue early; verify later

    float cc0 = dropline - simCur.x;
    float cc1 = dropline - simCur.y;
    float cc2 = dropline - simCur.z;
    float cc3 = dropline - simCur.w;

    // left neighbor of lane's first col = previous row's base (exact identity)
    float d0 = base + cc0;
    float d1 = prev0 + cc1;
    float d2 = prev1 + cc2;
    float d3 = prev2 + cc3;
    float n0 = fminf(d0, prev0);
    float n1 = fminf(d1, prev1);
    float n2 = fminf(d2, prev2);
    float n3 = fminf(d3, prev3);
    float p0 = n0;
    float p1 = fminf(p0, n1);
    float p2 = fminf(p1, n2);
    float p3 = fminf(p2, n3);

    // warp inclusive min-scan of lane totals, then exclusive prefix E
    float S = p3;
#pragma unroll
    for (int o = 1; o < 32; o <<= 1) {
        float v = __shfl_up_sync(0xffffffffu, S, o);
        if (lane >= o) S = fminf(S, v);
    }
    float E = __shfl_up_sync(0xffffffffu, S, 1);

    if (b != 0) { while (incoming > 0.5f) incoming = *pb; }

    float nbase = (lane == 0) ? incoming : fminf(incoming, E);
    float D0 = fminf(nbase, p0);
    float D1 = fminf(nbase, p1);
    float D2 = fminf(nbase, p2);
    float D3 = fminf(nbase, p3);

    if (lane == 31 && b < NB - 1) {
        volatile float* q = (volatile float*)&g_bound[(size_t)i * NB + (b + 1)];
        *q = D3;
    }

    bool df0 = (D0 == d0); bool uf0 = (!df0) && (D0 == prev0);
    bool df1 = (D1 == d1); bool uf1 = (!df1) && (D1 == prev1);
    bool df2 = (D2 == d2); bool uf2 = (!df2) && (D2 == prev2);
    bool df3 = (D3 == d3); bool uf3 = (!df3) && (D3 == prev3);
    unsigned byte = (df0 ? 1u : 0u) | (df1 ? 2u : 0u) | (df2 ? 4u : 0u) | (df3 ? 8u : 0u)
                  | (uf0 ? 16u : 0u) | (uf1 ? 32u : 0u) | (uf2 ? 64u : 0u) | (uf3 ? 128u : 0u);
    decp[(size_t)(i - 1) * 32] = (unsigned char)byte;   // coalesced: 32B/warp/row

    prev0 = D0; prev1 = D1; prev2 = D2; prev3 = D3;
    base = nbase;
}

__global__ void __launch_bounds__(32, 1) dp_kernel(int rows) {   // rows even
    const int b = blockIdx.x;
    const int lane = threadIdx.x;
    const int c0 = b * CW;
    const float dropline = g_dropline;
    const float* gsim = g_sim + c0 + 4 * lane;
    unsigned char* decp = g_dec + (size_t)b * NN * 32 + lane;

    float prev0 = 0.f, prev1 = 0.f, prev2 = 0.f, prev3 = 0.f;
    float base = 0.f;   // D[0][...] row is all zeros

    float4 A = *reinterpret_cast<const float4*>(gsim);                      // sim row 0
    float4 B = *reinterpret_cast<const float4*>(gsim + (size_t)1 * MM);     // sim row 1

    for (int i = 1; i <= rows; i += 2) {
        float4 cur = A;
        if (i + 1 < rows)
            A = *reinterpret_cast<const float4*>(gsim + (size_t)(i + 1) * MM);
        dp_row(b, lane, i, dropline, cur, prev0, prev1, prev2, prev3, base, decp);

        cur = B;
        if (i + 2 < rows)
            B = *reinterpret_cast<const float4*>(gsim + (size_t)(i + 2) * MM);
        dp_row(b, lane, i + 1, dropline, cur, prev0, prev1, prev2, prev3, base, decp);
    }
}

// ---------------- traceback: 448-row tiles, u64 nibble repack, left-run skipping ----------------
// Natural word W (strip-local cols 32w4..32w4+31, strip = W>>2, w4 = W&3):
// 8 bytes at g_dec[strip*NN*32 + row*32 + w4*8].
__device__ __forceinline__ unsigned nib_compact(unsigned long long x) {
    x &= 0x0F0F0F0F0F0F0F0Full;
    x = (x | (x >> 4))  & 0x00FF00FF00FF00FFull;
    x = (x | (x >> 8))  & 0x0000FFFF0000FFFFull;
    x = (x | (x >> 16));
    return (unsigned)x;
}

__global__ void traceback(float* __restrict__ out) {
    __shared__ uint2    s_du[TBR * 8];
    __shared__ unsigned s_c[TBR * 8];
    __shared__ int s_ij[2];
    int t = threadIdx.x;    // 256 threads
    int i = NN, j = MM;
    while (i > 0 && j > 0) {
        int ilo = (i - (TBR - 1) > 1) ? (i - (TBR - 1)) : 1;
        int jbhi = (j - 1) >> 7;                       // 128-col strip of current jj
        int jblo = (jbhi - 1 > 0) ? (jbhi - 1) : 0;    // stage 2 strips
        int rows = i - ilo + 1;
        for (int idx = t; idx < rows * 8; idx += 256) {
            int r = idx >> 3, wq = idx & 7;            // natural word 0..7 across 2 strips
            int strip = jblo + (wq >> 2), w4 = wq & 3;
            size_t boff = (size_t)strip * ((size_t)NN * 32)
                        + (size_t)(ilo - 1 + r) * 32 + (size_t)w4 * 8;
            unsigned long long Bv = *reinterpret_cast<const unsigned long long*>(&g_dec[boff]);
            unsigned dw = nib_compact(Bv);
            unsigned uw = nib_compact(Bv >> 4);
            s_du[r * 8 + wq] = make_uint2(dw, uw);
            s_c[r * 8 + wq] = dw | uw;
        }
        __syncthreads();
        if (t == 0) {
            int jlo = jblo * 128 + 1;                  // smallest j inside the staged strips
            while (i >= ilo && j >= jlo) {
                int jj = j - 1;
                int r = i - ilo;
                int w = (jj >> 5) - jblo * 4;          // 0..7
                int bit = jj & 31;
                uint2 du = s_du[r * 8 + w];
                if ((du.x >> bit) & 1u) {
                    out[(size_t)(i - 1) * MM + jj] = 1.0f; --i; --j;
                } else if ((du.y >> bit) & 1u) {
                    --i;
                } else {
                    unsigned m = s_c[r * 8 + w] & ((bit == 0) ? 0u : ((1u << bit) - 1u));
                    for (;;) {
                        if (m) { int nb = 31 - __clz(m); j = (jblo * 4 + w) * 32 + nb + 1; break; }
                        if (w == 0) { j = jlo - 1; break; }
                        --w;
                        m = s_c[r * 8 + w];
                    }
                }
            }
            s_ij[0] = i; s_ij[1] = j;
        }
        __syncthreads();
        i = s_ij[0]; j = s_ij[1];
        __syncthreads();
    }
}

// ---------------- launch ----------------
extern "C" void kernel_launch(void* const* d_in, const int* in_sizes, int n_in,
                              void* d_out, int out_size) {
    (void)in_sizes; (void)n_in; (void)out_size;
    const float* text  = (const float*)d_in[2];
    const float* event = (const float*)d_in[3];
    float* out = (float*)d_out;

    // Launch #4 = dp probe (512 rows) -> ncu profiles it (dur/512 = new Tc).
    // Timing data-independent; writes only g_dec (fully overwritten by real DP)
    // and g_bound (reset by init_state below).
    init_state<<<256, 256>>>();
    normalize_rows<<<NN, 256>>>(text, 0);
    normalize_rows<<<MM, 256>>>(event, 1);
    dp_kernel<<<NB, 32>>>(512);           // PROBE
    init_state<<<256, 256>>>();
    gemm_nt<<<dim3(32, 32), 256>>>();
    for (int p = 0; p < 4; ++p) {
        int shift = 24 - 8 * p;
        hist_pass<<<2048, 256>>>(shift);
        select_pass<<<1, 256>>>(shift, p == 3 ? 1 : 0);
    }
    fill_zero4<<<2048, 256>>>((float4*)out, (size_t)NN * MM / 4);
    dp_kernel<<<NB, 32>>>(NN);            // real DP
    traceback<<<1, 256>>>(out);
}

// round 11
// speedup vs baseline: 1.7579x; 1.3622x over previous
#include <cuda_runtime.h>
#include <cstdint>
#include <cstddef>

#define NN 4096
#define MM 4096
#define DD 1024
// k = int(4096*4096*0.3) = 5033164 ; ascending 0-based rank = 16777216 - k
#define RANK_ASC 11744052u
#define NB 32          // DP column chunks
#define CW 128         // columns per chunk
#define TBR 448        // traceback tile rows
#define NG (NN / 4)    // handoff groups (4 rows each)

// ---------------- static device scratch (no allocations allowed) ----------------
__device__ float    g_z[(size_t)NN * DD];
__device__ float    g_x[(size_t)MM * DD];
__device__ float    g_sim[(size_t)NN * MM];
// decision bytes, coalesced per block: g_dec[block*NN*32 + row*32 + lane]
__device__ unsigned char g_dec[(size_t)NN * 1024];
// boundary handoff, 4 rows per float4: g_bound2[b*NG + g] = D[4g+1..4g+4][b*CW]
__device__ float4   g_bound2[(size_t)NB * NG];
__device__ unsigned g_hist[256];
__device__ unsigned g_sel[2];   // [0]=prefix key, [1]=remaining rank
__device__ float    g_dropline;

// ---------------- helpers ----------------
__device__ __forceinline__ unsigned fkey(float f) {
    unsigned u = __float_as_uint(f);
    return (u & 0x80000000u) ? ~u : (u | 0x80000000u);
}
// volatile (strong) 128-bit handoff ops — single instruction each.
__device__ __forceinline__ float4 ldv4(const float4* p) {
    float4 v;
    asm volatile("ld.volatile.global.v4.f32 {%0,%1,%2,%3}, [%4];"
                 : "=f"(v.x), "=f"(v.y), "=f"(v.z), "=f"(v.w) : "l"(p));
    return v;
}
__device__ __forceinline__ void stv4(float4* p, float4 v) {
    asm volatile("st.volatile.global.v4.f32 [%0], {%1,%2,%3,%4};"
                 :: "l"(p), "f"(v.x), "f"(v.y), "f"(v.z), "f"(v.w));
}

// ---------------- init (must reset all mutable state every replay) ----------------
__global__ void init_state() {
    int idx = blockIdx.x * blockDim.x + threadIdx.x;
    if (idx < 256) g_hist[idx] = 0u;
    if (idx == 0) { g_sel[0] = 0u; g_sel[1] = RANK_ASC; }
    int total = NB * NG;
    float4 s; s.x = s.y = s.z = s.w = 1.0f;   // sentinel: real D values are <= 0
    for (int i = idx; i < total; i += gridDim.x * blockDim.x)
        g_bound2[i] = s;
}

__global__ void fill_zero4(float4* __restrict__ out, size_t n4) {
    size_t stride = (size_t)gridDim.x * blockDim.x;
    float4 z; z.x = z.y = z.z = z.w = 0.f;
    for (size_t i = blockIdx.x * (size_t)blockDim.x + threadIdx.x; i < n4; i += stride)
        out[i] = z;
}

// ---------------- row normalize ----------------
__global__ void normalize_rows(const float* __restrict__ in, int which) {
    int row = blockIdx.x;
    int t = threadIdx.x;                 // 256 threads
    const float* p = in + (size_t)row * DD;
    float s = 0.f;
#pragma unroll
    for (int k = 0; k < 4; k++) { float v = p[t + k * 256]; s = fmaf(v, v, s); }
    __shared__ float red[256];
    red[t] = s; __syncthreads();
    for (int o = 128; o > 0; o >>= 1) { if (t < o) red[t] += red[t + o]; __syncthreads(); }
    float nrm = sqrtf(red[0]);
    float* q = (which == 0 ? g_z : g_x) + (size_t)row * DD;
#pragma unroll
    for (int k = 0; k < 4; k++) q[t + k * 256] = p[t + k * 256] / nrm;
}

// ---------------- f32 NT GEMM, double-buffered smem, f32x2 packed FMA ----------------
// Accumulation order identical to scalar version => bitwise-identical sim.
__global__ void __launch_bounds__(256) gemm_nt() {
    __shared__ __align__(16) float As[2][16][132];
    __shared__ __align__(16) float Bs[2][16][132];
    int tid = threadIdx.x;
    int ty = tid >> 4;   // 0..15
    int tx = tid & 15;   // 0..15
    int bi = blockIdx.y * 128;
    int bj = blockIdx.x * 128;

    int arow0 = tid >> 2;            // 0..63
    int a4 = (tid & 3) * 4;          // 0,4,8,12

    unsigned long long acc2[4][8];
#pragma unroll
    for (int rp = 0; rp < 4; rp++)
#pragma unroll
        for (int c = 0; c < 8; c++) acc2[rp][c] = 0ull;

    {
        float4 va0 = *reinterpret_cast<const float4*>(&g_z[(size_t)(bi + arow0) * DD + a4]);
        float4 va1 = *reinterpret_cast<const float4*>(&g_z[(size_t)(bi + arow0 + 64) * DD + a4]);
        float4 vb0 = *reinterpret_cast<const float4*>(&g_x[(size_t)(bj + arow0) * DD + a4]);
        float4 vb1 = *reinterpret_cast<const float4*>(&g_x[(size_t)(bj + arow0 + 64) * DD + a4]);
        As[0][a4 + 0][arow0] = va0.x; As[0][a4 + 1][arow0] = va0.y;
        As[0][a4 + 2][arow0] = va0.z; As[0][a4 + 3][arow0] = va0.w;
        As[0][a4 + 0][arow0 + 64] = va1.x; As[0][a4 + 1][arow0 + 64] = va1.y;
        As[0][a4 + 2][arow0 + 64] = va1.z; As[0][a4 + 3][arow0 + 64] = va1.w;
        Bs[0][a4 + 0][arow0] = vb0.x; Bs[0][a4 + 1][arow0] = vb0.y;
        Bs[0][a4 + 2][arow0] = vb0.z; Bs[0][a4 + 3][arow0] = vb0.w;
        Bs[0][a4 + 0][arow0 + 64] = vb1.x; Bs[0][a4 + 1][arow0 + 64] = vb1.y;
        Bs[0][a4 + 2][arow0 + 64] = vb1.z; Bs[0][a4 + 3][arow0 + 64] = vb1.w;
    }
    __syncthreads();

    int s = 0;
    for (int k0 = 0; k0 < DD; k0 += 16, s ^= 1) {
        float4 va0, va1, vb0, vb1;
        bool more = (k0 + 16 < DD);
        if (more) {
            int kn = k0 + 16;
            va0 = *reinterpret_cast<const float4*>(&g_z[(size_t)(bi + arow0) * DD + kn + a4]);
            va1 = *reinterpret_cast<const float4*>(&g_z[(size_t)(bi + arow0 + 64) * DD + kn + a4]);
            vb0 = *reinterpret_cast<const float4*>(&g_x[(size_t)(bj + arow0) * DD + kn + a4]);
            vb1 = *reinterpret_cast<const float4*>(&g_x[(size_t)(bj + arow0 + 64) * DD + kn + a4]);
        }
#pragma unroll
        for (int kk = 0; kk < 16; kk++) {
            const ulonglong2* ap2 = reinterpret_cast<const ulonglong2*>(&As[s][kk][ty * 8]);
            ulonglong2 aa = ap2[0], ab = ap2[1];
            unsigned long long a2[4];
            a2[0] = aa.x; a2[1] = aa.y; a2[2] = ab.x; a2[3] = ab.y;
            const float4* bp = reinterpret_cast<const float4*>(&Bs[s][kk][tx * 8]);
            float4 b0 = bp[0], b1 = bp[1];
            float bbv[8];
            bbv[0] = b0.x; bbv[1] = b0.y; bbv[2] = b0.z; bbv[3] = b0.w;
            bbv[4] = b1.x; bbv[5] = b1.y; bbv[6] = b1.z; bbv[7] = b1.w;
            unsigned long long b2[8];
#pragma unroll
            for (int c = 0; c < 8; c++)
                asm("mov.b64 %0, {%1, %1};" : "=l"(b2[c]) : "r"(__float_as_uint(bbv[c])));
#pragma unroll
            for (int c = 0; c < 8; c++)
#pragma unroll
                for (int rp = 0; rp < 4; rp++)
                    asm("fma.rn.f32x2 %0, %1, %2, %0;"
                        : "+l"(acc2[rp][c]) : "l"(a2[rp]), "l"(b2[c]));
        }
        __syncthreads();
        if (more) {
            int d = s ^ 1;
            As[d][a4 + 0][arow0] = va0.x; As[d][a4 + 1][arow0] = va0.y;
            As[d][a4 + 2][arow0] = va0.z; As[d][a4 + 3][arow0] = va0.w;
            As[d][a4 + 0][arow0 + 64] = va1.x; As[d][a4 + 1][arow0 + 64] = va1.y;
            As[d][a4 + 2][arow0 + 64] = va1.z; As[d][a4 + 3][arow0 + 64] = va1.w;
            Bs[d][a4 + 0][arow0] = vb0.x; Bs[d][a4 + 1][arow0] = vb0.y;
            Bs[d][a4 + 2][arow0] = vb0.z; Bs[d][a4 + 3][arow0] = vb0.w;
            Bs[d][a4 + 0][arow0 + 64] = vb1.x; Bs[d][a4 + 1][arow0 + 64] = vb1.y;
            Bs[d][a4 + 2][arow0 + 64] = vb1.z; Bs[d][a4 + 3][arow0 + 64] = vb1.w;
            __syncthreads();
        }
    }
#pragma unroll
    for (int rp = 0; rp < 4; rp++) {
        float lo[8], hi[8];
#pragma unroll
        for (int c = 0; c < 8; c++) {
            lo[c] = __uint_as_float((unsigned)(acc2[rp][c] & 0xffffffffull));
            hi[c] = __uint_as_float((unsigned)(acc2[rp][c] >> 32));
        }
        float* dst0 = &g_sim[(size_t)(bi + ty * 8 + 2 * rp) * MM + (bj + tx * 8)];
        float* dst1 = &g_sim[(size_t)(bi + ty * 8 + 2 * rp + 1) * MM + (bj + tx * 8)];
        float4 o;
        o.x = lo[0]; o.y = lo[1]; o.z = lo[2]; o.w = lo[3];
        *reinterpret_cast<float4*>(dst0) = o;
        o.x = lo[4]; o.y = lo[5]; o.z = lo[6]; o.w = lo[7];
        *reinterpret_cast<float4*>(dst0 + 4) = o;
        o.x = hi[0]; o.y = hi[1]; o.z = hi[2]; o.w = hi[3];
        *reinterpret_cast<float4*>(dst1) = o;
        o.x = hi[4]; o.y = hi[5]; o.z = hi[6]; o.w = hi[7];
        *reinterpret_cast<float4*>(dst1 + 4) = o;
    }
}

// ---------------- exact radix select (privatized per-warp hists) ----------------
__global__ void hist_pass(int shift) {
    __shared__ unsigned sh[8][256];
    int t = threadIdx.x;
    int wid = t >> 5;
    for (int k = t; k < 8 * 256; k += 256) ((unsigned*)sh)[k] = 0u;
    __syncthreads();
    unsigned prefix = g_sel[0];
    int above = shift + 8;
    size_t stride = (size_t)gridDim.x * blockDim.x;
    size_t total = (size_t)NN * MM;
    for (size_t i = blockIdx.x * (size_t)blockDim.x + threadIdx.x; i < total; i += stride) {
        unsigned u = fkey(g_sim[i]);
        bool ok = (above >= 32) || ((u >> above) == (prefix >> above));
        if (ok) atomicAdd(&sh[wid][(u >> shift) & 255u], 1u);
    }
    __syncthreads();
    unsigned tot = 0;
#pragma unroll
    for (int wq = 0; wq < 8; wq++) tot += sh[wq][t];
    if (tot) atomicAdd(&g_hist[t], tot);
}

__global__ void select_pass(int shift, int last) {
    __shared__ unsigned cnt[256];
    int t = threadIdx.x;
    cnt[t] = g_hist[t];
    g_hist[t] = 0u;   // reset for the next pass
    __syncthreads();
    if (t == 0) {
        unsigned rank = g_sel[1], cum = 0; int bin = 255;
        for (int b = 0; b < 256; b++) {
            unsigned c = cnt[b];
            if (cum + c > rank) { bin = b; break; }
            cum += c;
        }
        g_sel[0] |= ((unsigned)bin) << shift;
        g_sel[1] = rank - cum;
        if (last) {
            unsigned u = g_sel[0];
            unsigned bits = (u & 0x80000000u) ? (u & 0x7FFFFFFFu) : ~u;
            g_dropline = __uint_as_float(bits);
        }
    }
}

// ---------------- NW DP wavefront: volatile 4-row-batched handoff, base-carry ----------------
// Math byte-identical to the R9-passing version; only the handoff batching changed.
__device__ __forceinline__ float dp_row(
    int lane, int i, float dropline, float4 simCur, float incoming,
    float& prev0, float& prev1, float& prev2, float& prev3,
    float& bcar, unsigned char* decp)
{
    float cc0 = dropline - simCur.x;
    float cc1 = dropline - simCur.y;
    float cc2 = dropline - simCur.z;
    float cc3 = dropline - simCur.w;

    float d0 = bcar + cc0;     // left neighbor = previous row's base (exact identity)
    float d1 = prev0 + cc1;
    float d2 = prev1 + cc2;
    float d3 = prev2 + cc3;
    float n0 = fminf(d0, prev0);
    float n1 = fminf(d1, prev1);
    float n2 = fminf(d2, prev2);
    float n3 = fminf(d3, prev3);
    float p0 = n0;
    float p1 = fminf(p0, n1);
    float p2 = fminf(p1, n2);
    float p3 = fminf(p2, n3);

    // warp inclusive min-scan of lane totals
    float S = p3;
#pragma unroll
    for (int o = 1; o < 32; o <<= 1) {
        float v = __shfl_up_sync(0xffffffffu, S, o);
        if (lane >= o) S = fminf(S, v);
    }
    float E = __shfl_up_sync(0xffffffffu, S, 1);   // exclusive prefix (lanes > 0)

    float nbase = (lane == 0) ? incoming : fminf(incoming, E);
    float D0 = fminf(nbase, p0);
    float D1 = fminf(nbase, p1);
    float D2 = fminf(nbase, p2);
    float D3 = fminf(nbase, p3);

    bool df0 = (D0 == d0); bool uf0 = (!df0) && (D0 == prev0);
    bool df1 = (D1 == d1); bool uf1 = (!df1) && (D1 == prev1);
    bool df2 = (D2 == d2); bool uf2 = (!df2) && (D2 == prev2);
    bool df3 = (D3 == d3); bool uf3 = (!df3) && (D3 == prev3);
    unsigned byte = (df0 ? 1u : 0u) | (df1 ? 2u : 0u) | (df2 ? 4u : 0u) | (df3 ? 8u : 0u)
                  | (uf0 ? 16u : 0u) | (uf1 ? 32u : 0u) | (uf2 ? 64u : 0u) | (uf3 ? 128u : 0u);
    decp[(size_t)(i - 1) * 32] = (unsigned char)byte;   // coalesced: 32B/warp/row

    prev0 = D0; prev1 = D1; prev2 = D2; prev3 = D3;
    bcar = nbase;
    return D3;
}

__global__ void __launch_bounds__(32, 1) dp_kernel(int rows) {   // rows % 4 == 0
    const int b = blockIdx.x;
    const int lane = threadIdx.x;
    const int c0 = b * CW;
    const float dropline = g_dropline;
    const float* gsim = g_sim + c0 + 4 * lane;
    unsigned char* decp = g_dec + (size_t)b * NN * 32 + lane;

    float prev0 = 0.f, prev1 = 0.f, prev2 = 0.f, prev3 = 0.f;
    float bcar = 0.f;   // D[0][...] row is all zeros

    int ng = rows >> 2;
    // preload group 0's sim rows
    float4 s0 = *reinterpret_cast<const float4*>(gsim);
    float4 s1 = *reinterpret_cast<const float4*>(gsim + (size_t)1 * MM);
    float4 s2 = *reinterpret_cast<const float4*>(gsim + (size_t)2 * MM);
    float4 s3 = *reinterpret_cast<const float4*>(gsim + (size_t)3 * MM);

    for (int g = 0; g < ng; ++g) {
        float4 n0, n1, n2, n3;
        if (g + 1 < ng) {   // prefetch next group's sim rows (latency hidden under poll+compute)
            const float* nbase = gsim + (size_t)(4 * (g + 1)) * MM;
            n0 = *reinterpret_cast<const float4*>(nbase);
            n1 = *reinterpret_cast<const float4*>(nbase + (size_t)1 * MM);
            n2 = *reinterpret_cast<const float4*>(nbase + (size_t)2 * MM);
            n3 = *reinterpret_cast<const float4*>(nbase + (size_t)3 * MM);
        }
        float4 inc4; inc4.x = inc4.y = inc4.z = inc4.w = 0.f;
        if (b != 0) {
            const float4* pp = &g_bound2[(size_t)b * NG + g];
            inc4 = ldv4(pp);
            while (inc4.x > 0.5f || inc4.y > 0.5f || inc4.z > 0.5f || inc4.w > 0.5f)
                inc4 = ldv4(pp);
        }
        int i = 4 * g + 1;
        float4 out4;
        out4.x = dp_row(lane, i + 0, dropline, s0, inc4.x, prev0, prev1, prev2, prev3, bcar, decp);
        out4.y = dp_row(lane, i + 1, dropline, s1, inc4.y, prev0, prev1, prev2, prev3, bcar, decp);
        out4.z = dp_row(lane, i + 2, dropline, s2, inc4.z, prev0, prev1, prev2, prev3, bcar, decp);
        out4.w = dp_row(lane, i + 3, dropline, s3, inc4.w, prev0, prev1, prev2, prev3, bcar, decp);
        if (lane == 31 && b < NB - 1)
            stv4(&g_bound2[(size_t)(b + 1) * NG + g], out4);
        s0 = n0; s1 = n1; s2 = n2; s3 = n3;
    }
}

// ---------------- traceback: 448-row tiles, u64 nibble repack, left-run skipping ----------------
__device__ __forceinline__ unsigned nib_compact(unsigned long long x) {
    x &= 0x0F0F0F0F0F0F0F0Full;
    x = (x | (x >> 4))  & 0x00FF00FF00FF00FFull;
    x = (x | (x >> 8))  & 0x0000FFFF0000FFFFull;
    x = (x | (x >> 16));
    return (unsigned)x;
}

__global__ void traceback(float* __restrict__ out) {
    __shared__ uint2    s_du[TBR * 8];
    __shared__ unsigned s_c[TBR * 8];
    __shared__ int s_ij[2];
    int t = threadIdx.x;    // 256 threads
    int i = NN, j = MM;
    while (i > 0 && j > 0) {
        int ilo = (i - (TBR - 1) > 1) ? (i - (TBR - 1)) : 1;
        int jbhi = (j - 1) >> 7;                       // 128-col strip of current jj
        int jblo = (jbhi - 1 > 0) ? (jbhi - 1) : 0;    // stage 2 strips
        int rows = i - ilo + 1;
        for (int idx = t; idx < rows * 8; idx += 256) {
            int r = idx >> 3, wq = idx & 7;            // natural word 0..7 across 2 strips
            int strip = jblo + (wq >> 2), w4 = wq & 3;
            size_t boff = (size_t)strip * ((size_t)NN * 32)
                        + (size_t)(ilo - 1 + r) * 32 + (size_t)w4 * 8;
            unsigned long long Bv = *reinterpret_cast<const unsigned long long*>(&g_dec[boff]);
            unsigned dw = nib_compact(Bv);
            unsigned uw = nib_compact(Bv >> 4);
            s_du[r * 8 + wq] = make_uint2(dw, uw);
            s_c[r * 8 + wq] = dw | uw;
        }
        __syncthreads();
        if (t == 0) {
            int jlo = jblo * 128 + 1;                  // smallest j inside the staged strips
            while (i >= ilo && j >= jlo) {
                int jj = j - 1;
                int r = i - ilo;
                int w = (jj >> 5) - jblo * 4;          // 0..7
                int bit = jj & 31;
                uint2 du = s_du[r * 8 + w];
                if ((du.x >> bit) & 1u) {
                    out[(size_t)(i - 1) * MM + jj] = 1.0f; --i; --j;
                } else if ((du.y >> bit) & 1u) {
                    --i;
                } else {
                    unsigned m = s_c[r * 8 + w] & ((bit == 0) ? 0u : ((1u << bit) - 1u));
                    for (;;) {
                        if (m) { int nb = 31 - __clz(m); j = (jblo * 4 + w) * 32 + nb + 1; break; }
                        if (w == 0) { j = jlo - 1; break; }
                        --w;
                        m = s_c[r * 8 + w];
                    }
                }
            }
            s_ij[0] = i; s_ij[1] = j;
        }
        __syncthreads();
        i = s_ij[0]; j = s_ij[1];
        __syncthreads();
    }
}

// ---------------- launch ----------------
extern "C" void kernel_launch(void* const* d_in, const int* in_sizes, int n_in,
                              void* d_out, int out_size) {
    (void)in_sizes; (void)n_in; (void)out_size;
    const float* text  = (const float*)d_in[2];
    const float* event = (const float*)d_in[3];
    float* out = (float*)d_out;

    // Launch #4 = dp probe (512 rows) -> ncu profiles it (dur/512 = batched Tc).
    // Timing data-independent; writes only g_dec (fully overwritten by real DP)
    // and g_bound2 (reset by init_state below). D <= 0 invariant holds for any
    // inputs (fminf discards NaN; row 0 = 0), so no sentinel deadlock.
    init_state<<<256, 256>>>();
    normalize_rows<<<NN, 256>>>(text, 0);
    normalize_rows<<<MM, 256>>>(event, 1);
    dp_kernel<<<NB, 32>>>(512);           // PROBE
    init_state<<<256, 256>>>();
    gemm_nt<<<dim3(32, 32), 256>>>();
    for (int p = 0; p < 4; ++p) {
        int shift = 24 - 8 * p;
        hist_pass<<<2048, 256>>>(shift);
        select_pass<<<1, 256>>>(shift, p == 3 ? 1 : 0);
    }
    fill_zero4<<<2048, 256>>>((float4*)out, (size_t)NN * MM / 4);
    dp_kernel<<<NB, 32>>>(NN);            // real DP
    traceback<<<1, 256>>>(out);
}

// round 13
// speedup vs baseline: 1.9078x; 1.0853x over previous
#include <cuda_runtime.h>
#include <cstdint>
#include <cstddef>

#define NN 4096
#define MM 4096
#define DD 1024
// k = int(4096*4096*0.3) = 5033164 ; ascending 0-based rank = 16777216 - k
#define RANK_ASC 11744052u
#define NB 32          // DP column chunks
#define CW 128         // columns per chunk
#define TBR 448        // traceback tile rows
#define NG (NN / 4)    // handoff groups (4 rows each)

// ---------------- static device scratch (no allocations allowed) ----------------
__device__ float    g_z[(size_t)NN * DD];
__device__ float    g_x[(size_t)MM * DD];
__device__ float    g_sim[(size_t)NN * MM];
// decision bytes, coalesced per block: g_dec[block*NN*32 + row*32 + lane]
__device__ unsigned char g_dec[(size_t)NN * 1024];
// boundary handoff, 4 rows per float4: g_bound2[b*NG + g] = D[4g+1..4g+4][b*CW]
__device__ float4   g_bound2[(size_t)NB * NG];
__device__ unsigned g_hist[256];
__device__ unsigned g_sel[2];   // [0]=prefix key, [1]=remaining rank
__device__ float    g_dropline;

// ---------------- helpers ----------------
__device__ __forceinline__ unsigned fkey(float f) {
    unsigned u = __float_as_uint(f);
    return (u & 0x80000000u) ? ~u : (u | 0x80000000u);
}
// volatile (strong) 128-bit handoff ops — single instruction each.
__device__ __forceinline__ float4 ldv4(const float4* p) {
    float4 v;
    asm volatile("ld.volatile.global.v4.f32 {%0,%1,%2,%3}, [%4];"
                 : "=f"(v.x), "=f"(v.y), "=f"(v.z), "=f"(v.w) : "l"(p));
    return v;
}
__device__ __forceinline__ void stv4(float4* p, float4 v) {
    asm volatile("st.volatile.global.v4.f32 [%0], {%1,%2,%3,%4};"
                 :: "l"(p), "f"(v.x), "f"(v.y), "f"(v.z), "f"(v.w));
}

// ---------------- init (must reset all mutable state every replay) ----------------
__global__ void init_state() {
    int idx = blockIdx.x * blockDim.x + threadIdx.x;
    if (idx < 256) g_hist[idx] = 0u;
    if (idx == 0) { g_sel[0] = 0u; g_sel[1] = RANK_ASC; }
    int total = NB * NG;
    float4 s; s.x = s.y = s.z = s.w = 1.0f;   // sentinel: real D values are <= 0
    for (int i = idx; i < total; i += gridDim.x * blockDim.x)
        g_bound2[i] = s;
}

__global__ void fill_zero4(float4* __restrict__ out, size_t n4) {
    size_t stride = (size_t)gridDim.x * blockDim.x;
    float4 z; z.x = z.y = z.z = z.w = 0.f;
    for (size_t i = blockIdx.x * (size_t)blockDim.x + threadIdx.x; i < n4; i += stride)
        out[i] = z;
}

// ---------------- row normalize ----------------
__global__ void normalize_rows(const float* __restrict__ in, int which) {
    int row = blockIdx.x;
    int t = threadIdx.x;                 // 256 threads
    const float* p = in + (size_t)row * DD;
    float s = 0.f;
#pragma unroll
    for (int k = 0; k < 4; k++) { float v = p[t + k * 256]; s = fmaf(v, v, s); }
    __shared__ float red[256];
    red[t] = s; __syncthreads();
    for (int o = 128; o > 0; o >>= 1) { if (t < o) red[t] += red[t + o]; __syncthreads(); }
    float nrm = sqrtf(red[0]);
    float* q = (which == 0 ? g_z : g_x) + (size_t)row * DD;
#pragma unroll
    for (int k = 0; k < 4; k++) q[t + k * 256] = p[t + k * 256] / nrm;
}

// ---------------- f32 NT GEMM, double-buffered smem, f32x2 packed FMA ----------------
// Accumulation order identical to scalar version => bitwise-identical sim.
__global__ void __launch_bounds__(256) gemm_nt() {
    __shared__ __align__(16) float As[2][16][132];
    __shared__ __align__(16) float Bs[2][16][132];
    int tid = threadIdx.x;
    int ty = tid >> 4;   // 0..15
    int tx = tid & 15;   // 0..15
    int bi = blockIdx.y * 128;
    int bj = blockIdx.x * 128;

    int arow0 = tid >> 2;            // 0..63
    int a4 = (tid & 3) * 4;          // 0,4,8,12

    unsigned long long acc2[4][8];
#pragma unroll
    for (int rp = 0; rp < 4; rp++)
#pragma unroll
        for (int c = 0; c < 8; c++) acc2[rp][c] = 0ull;

    {
        float4 va0 = *reinterpret_cast<const float4*>(&g_z[(size_t)(bi + arow0) * DD + a4]);
        float4 va1 = *reinterpret_cast<const float4*>(&g_z[(size_t)(bi + arow0 + 64) * DD + a4]);
        float4 vb0 = *reinterpret_cast<const float4*>(&g_x[(size_t)(bj + arow0) * DD + a4]);
        float4 vb1 = *reinterpret_cast<const float4*>(&g_x[(size_t)(bj + arow0 + 64) * DD + a4]);
        As[0][a4 + 0][arow0] = va0.x; As[0][a4 + 1][arow0] = va0.y;
        As[0][a4 + 2][arow0] = va0.z; As[0][a4 + 3][arow0] = va0.w;
        As[0][a4 + 0][arow0 + 64] = va1.x; As[0][a4 + 1][arow0 + 64] = va1.y;
        As[0][a4 + 2][arow0 + 64] = va1.z; As[0][a4 + 3][arow0 + 64] = va1.w;
        Bs[0][a4 + 0][arow0] = vb0.x; Bs[0][a4 + 1][arow0] = vb0.y;
        Bs[0][a4 + 2][arow0] = vb0.z; Bs[0][a4 + 3][arow0] = vb0.w;
        Bs[0][a4 + 0][arow0 + 64] = vb1.x; Bs[0][a4 + 1][arow0 + 64] = vb1.y;
        Bs[0][a4 + 2][arow0 + 64] = vb1.z; Bs[0][a4 + 3][arow0 + 64] = vb1.w;
    }
    __syncthreads();

    int s = 0;
    for (int k0 = 0; k0 < DD; k0 += 16, s ^= 1) {
        float4 va0, va1, vb0, vb1;
        bool more = (k0 + 16 < DD);
        if (more) {
            int kn = k0 + 16;
            va0 = *reinterpret_cast<const float4*>(&g_z[(size_t)(bi + arow0) * DD + kn + a4]);
            va1 = *reinterpret_cast<const float4*>(&g_z[(size_t)(bi + arow0 + 64) * DD + kn + a4]);
            vb0 = *reinterpret_cast<const float4*>(&g_x[(size_t)(bj + arow0) * DD + kn + a4]);
            vb1 = *reinterpret_cast<const float4*>(&g_x[(size_t)(bj + arow0 + 64) * DD + kn + a4]);
        }
#pragma unroll
        for (int kk = 0; kk < 16; kk++) {
            const ulonglong2* ap2 = reinterpret_cast<const ulonglong2*>(&As[s][kk][ty * 8]);
            ulonglong2 aa = ap2[0], ab = ap2[1];
            unsigned long long a2[4];
            a2[0] = aa.x; a2[1] = aa.y; a2[2] = ab.x; a2[3] = ab.y;
            const float4* bp = reinterpret_cast<const float4*>(&Bs[s][kk][tx * 8]);
            float4 b0 = bp[0], b1 = bp[1];
            float bbv[8];
            bbv[0] = b0.x; bbv[1] = b0.y; bbv[2] = b0.z; bbv[3] = b0.w;
            bbv[4] = b1.x; bbv[5] = b1.y; bbv[6] = b1.z; bbv[7] = b1.w;
            unsigned long long b2[8];
#pragma unroll
            for (int c = 0; c < 8; c++)
                asm("mov.b64 %0, {%1, %1};" : "=l"(b2[c]) : "r"(__float_as_uint(bbv[c])));
#pragma unroll
            for (int c = 0; c < 8; c++)
#pragma unroll
                for (int rp = 0; rp < 4; rp++)
                    asm("fma.rn.f32x2 %0, %1, %2, %0;"
                        : "+l"(acc2[rp][c]) : "l"(a2[rp]), "l"(b2[c]));
        }
        __syncthreads();
        if (more) {
            int d = s ^ 1;
            As[d][a4 + 0][arow0] = va0.x; As[d][a4 + 1][arow0] = va0.y;
            As[d][a4 + 2][arow0] = va0.z; As[d][a4 + 3][arow0] = va0.w;
            As[d][a4 + 0][arow0 + 64] = va1.x; As[d][a4 + 1][arow0 + 64] = va1.y;
            As[d][a4 + 2][arow0 + 64] = va1.z; As[d][a4 + 3][arow0 + 64] = va1.w;
            Bs[d][a4 + 0][arow0] = vb0.x; Bs[d][a4 + 1][arow0] = vb0.y;
            Bs[d][a4 + 2][arow0] = vb0.z; Bs[d][a4 + 3][arow0] = vb0.w;
            Bs[d][a4 + 0][arow0 + 64] = vb1.x; Bs[d][a4 + 1][arow0 + 64] = vb1.y;
            Bs[d][a4 + 2][arow0 + 64] = vb1.z; Bs[d][a4 + 3][arow0 + 64] = vb1.w;
            __syncthreads();
        }
    }
#pragma unroll
    for (int rp = 0; rp < 4; rp++) {
        float lo[8], hi[8];
#pragma unroll
        for (int c = 0; c < 8; c++) {
            lo[c] = __uint_as_float((unsigned)(acc2[rp][c] & 0xffffffffull));
            hi[c] = __uint_as_float((unsigned)(acc2[rp][c] >> 32));
        }
        float* dst0 = &g_sim[(size_t)(bi + ty * 8 + 2 * rp) * MM + (bj + tx * 8)];
        float* dst1 = &g_sim[(size_t)(bi + ty * 8 + 2 * rp + 1) * MM + (bj + tx * 8)];
        float4 o;
        o.x = lo[0]; o.y = lo[1]; o.z = lo[2]; o.w = lo[3];
        *reinterpret_cast<float4*>(dst0) = o;
        o.x = lo[4]; o.y = lo[5]; o.z = lo[6]; o.w = lo[7];
        *reinterpret_cast<float4*>(dst0 + 4) = o;
        o.x = hi[0]; o.y = hi[1]; o.z = hi[2]; o.w = hi[3];
        *reinterpret_cast<float4*>(dst1) = o;
        o.x = hi[4]; o.y = hi[5]; o.z = hi[6]; o.w = hi[7];
        *reinterpret_cast<float4*>(dst1 + 4) = o;
    }
}

// ---------------- exact radix select (privatized per-warp hists) ----------------
__global__ void hist_pass(int shift) {
    __shared__ unsigned sh[8][256];
    int t = threadIdx.x;
    int wid = t >> 5;
    for (int k = t; k < 8 * 256; k += 256) ((unsigned*)sh)[k] = 0u;
    __syncthreads();
    unsigned prefix = g_sel[0];
    int above = shift + 8;
    size_t stride = (size_t)gridDim.x * blockDim.x;
    size_t total = (size_t)NN * MM;
    for (size_t i = blockIdx.x * (size_t)blockDim.x + threadIdx.x; i < total; i += stride) {
        unsigned u = fkey(g_sim[i]);
        bool ok = (above >= 32) || ((u >> above) == (prefix >> above));
        if (ok) atomicAdd(&sh[wid][(u >> shift) & 255u], 1u);
    }
    __syncthreads();
    unsigned tot = 0;
#pragma unroll
    for (int wq = 0; wq < 8; wq++) tot += sh[wq][t];
    if (tot) atomicAdd(&g_hist[t], tot);
}

__global__ void select_pass(int shift, int last) {
    __shared__ unsigned cnt[256];
    int t = threadIdx.x;
    cnt[t] = g_hist[t];
    g_hist[t] = 0u;   // reset for the next pass
    __syncthreads();
    if (t == 0) {
        unsigned rank = g_sel[1], cum = 0; int bin = 255;
        for (int b = 0; b < 256; b++) {
            unsigned c = cnt[b];
            if (cum + c > rank) { bin = b; break; }
            cum += c;
        }
        g_sel[0] |= ((unsigned)bin) << shift;
        g_sel[1] = rank - cum;
        if (last) {
            unsigned u = g_sel[0];
            unsigned bits = (u & 0x80000000u) ? (u & 0x7FFFFFFFu) : ~u;
            g_dropline = __uint_as_float(bits);
        }
    }
}

// ---------------- NW DP wavefront: volatile 4-row-batched handoff with early peek ----------------
// Math byte-identical to the passing R11 version; only handoff read timing changed.
__device__ __forceinline__ float dp_row(
    int lane, int i, float dropline, float4 simCur, float incoming,
    float& prev0, float& prev1, float& prev2, float& prev3,
    float& bcar, unsigned char* decp)
{
    float cc0 = dropline - simCur.x;
    float cc1 = dropline - simCur.y;
    float cc2 = dropline - simCur.z;
    float cc3 = dropline - simCur.w;

    float d0 = bcar + cc0;     // left neighbor = previous row's base (exact identity)
    float d1 = prev0 + cc1;
    float d2 = prev1 + cc2;
    float d3 = prev2 + cc3;
    float n0 = fminf(d0, prev0);
    float n1 = fminf(d1, prev1);
    float n2 = fminf(d2, prev2);
    float n3 = fminf(d3, prev3);
    float p0 = n0;
    float p1 = fminf(p0, n1);
    float p2 = fminf(p1, n2);
    float p3 = fminf(p2, n3);

    // warp inclusive min-scan of lane totals
    float S = p3;
#pragma unroll
    for (int o = 1; o < 32; o <<= 1) {
        float v = __shfl_up_sync(0xffffffffu, S, o);
        if (lane >= o) S = fminf(S, v);
    }
    float E = __shfl_up_sync(0xffffffffu, S, 1);   // exclusive prefix (lanes > 0)

    float nbase = (lane == 0) ? incoming : fminf(incoming, E);
    float D0 = fminf(nbase, p0);
    float D1 = fminf(nbase, p1);
    float D2 = fminf(nbase, p2);
    float D3 = fminf(nbase, p3);

    bool df0 = (D0 == d0); bool uf0 = (!df0) && (D0 == prev0);
    bool df1 = (D1 == d1); bool uf1 = (!df1) && (D1 == prev1);
    bool df2 = (D2 == d2); bool uf2 = (!df2) && (D2 == prev2);
    bool df3 = (D3 == d3); bool uf3 = (!df3) && (D3 == prev3);
    unsigned byte = (df0 ? 1u : 0u) | (df1 ? 2u : 0u) | (df2 ? 4u : 0u) | (df3 ? 8u : 0u)
                  | (uf0 ? 16u : 0u) | (uf1 ? 32u : 0u) | (uf2 ? 64u : 0u) | (uf3 ? 128u : 0u);
    decp[(size_t)(i - 1) * 32] = (unsigned char)byte;   // coalesced: 32B/warp/row

    prev0 = D0; prev1 = D1; prev2 = D2; prev3 = D3;
    bcar = nbase;
    return D3;
}

__device__ __forceinline__ bool inc_ready(float4 v) {
    return !(v.x > 0.5f || v.y > 0.5f || v.z > 0.5f || v.w > 0.5f);
}

__global__ void __launch_bounds__(32, 1) dp_kernel(int rows) {   // rows % 4 == 0
    const int b = blockIdx.x;
    const int lane = threadIdx.x;
    const int c0 = b * CW;
    const float dropline = g_dropline;
    const float* gsim = g_sim + c0 + 4 * lane;
    unsigned char* decp = g_dec + (size_t)b * NN * 32 + lane;

    float prev0 = 0.f, prev1 = 0.f, prev2 = 0.f, prev3 = 0.f;
    float bcar = 0.f;   // D[0][...] row is all zeros

    int ng = rows >> 2;
    // preload group 0's sim rows
    float4 s0 = *reinterpret_cast<const float4*>(gsim);
    float4 s1 = *reinterpret_cast<const float4*>(gsim + (size_t)1 * MM);
    float4 s2 = *reinterpret_cast<const float4*>(gsim + (size_t)2 * MM);
    float4 s3 = *reinterpret_cast<const float4*>(gsim + (size_t)3 * MM);

    // incoming for group 0
    float4 inc4; inc4.x = inc4.y = inc4.z = inc4.w = 0.f;
    if (b != 0) {
        const float4* pp = &g_bound2[(size_t)b * NG + 0];
        inc4 = ldv4(pp);
        while (!inc_ready(inc4)) inc4 = ldv4(pp);
    }

    for (int g = 0; g < ng; ++g) {
        float4 n0, n1, n2, n3;
        if (g + 1 < ng) {   // prefetch next group's sim rows
            const float* nb2 = gsim + (size_t)(4 * (g + 1)) * MM;
            n0 = *reinterpret_cast<const float4*>(nb2);
            n1 = *reinterpret_cast<const float4*>(nb2 + (size_t)1 * MM);
            n2 = *reinterpret_cast<const float4*>(nb2 + (size_t)2 * MM);
            n3 = *reinterpret_cast<const float4*>(nb2 + (size_t)3 * MM);
        }
        int i = 4 * g + 1;
        float4 out4;
        out4.x = dp_row(lane, i + 0, dropline, s0, inc4.x, prev0, prev1, prev2, prev3, bcar, decp);
        out4.y = dp_row(lane, i + 1, dropline, s1, inc4.y, prev0, prev1, prev2, prev3, bcar, decp);
        out4.z = dp_row(lane, i + 2, dropline, s2, inc4.z, prev0, prev1, prev2, prev3, bcar, decp);
        out4.w = dp_row(lane, i + 3, dropline, s3, inc4.w, prev0, prev1, prev2, prev3, bcar, decp);

        // EARLY PEEK for group g+1 BEFORE the publish store: LD precedes ST in
        // program order, so the store doesn't stall it; if the peek already has
        // data (steady state), the post-store spin is skipped entirely.
        float4 nxt; nxt.x = nxt.y = nxt.z = nxt.w = 0.f;
        const float4* pp = &g_bound2[(size_t)b * NG + (g + 1)];
        bool need = (b != 0) && (g + 1 < ng);
        if (need) nxt = ldv4(pp);

        if (lane == 31 && b < NB - 1)
            stv4(&g_bound2[(size_t)(b + 1) * NG + g], out4);

        if (need) { while (!inc_ready(nxt)) nxt = ldv4(pp); }
        inc4 = nxt;
        s0 = n0; s1 = n1; s2 = n2; s3 = n3;
    }
}

// ---------------- traceback: 448-row tiles, u64 nibble repack, left-run skipping ----------------
__device__ __forceinline__ unsigned nib_compact(unsigned long long x) {
    x &= 0x0F0F0F0F0F0F0F0Full;
    x = (x | (x >> 4))  & 0x00FF00FF00FF00FFull;
    x = (x | (x >> 8))  & 0x0000FFFF0000FFFFull;
    x = (x | (x >> 16));
    return (unsigned)x;
}

__global__ void traceback(float* __restrict__ out) {
    __shared__ uint2    s_du[TBR * 8];
    __shared__ unsigned s_c[TBR * 8];
    __shared__ int s_ij[2];
    int t = threadIdx.x;    // 256 threads
    int i = NN, j = MM;
    while (i > 0 && j > 0) {
        int ilo = (i - (TBR - 1) > 1) ? (i - (TBR - 1)) : 1;
        int jbhi = (j - 1) >> 7;                       // 128-col strip of current jj
        int jblo = (jbhi - 1 > 0) ? (jbhi - 1) : 0;    // stage 2 strips
        int rows = i - ilo + 1;
        for (int idx = t; idx < rows * 8; idx += 256) {
            int r = idx >> 3, wq = idx & 7;            // natural word 0..7 across 2 strips
            int strip = jblo + (wq >> 2), w4 = wq & 3;
            size_t boff = (size_t)strip * ((size_t)NN * 32)
                        + (size_t)(ilo - 1 + r) * 32 + (size_t)w4 * 8;
            unsigned long long Bv = *reinterpret_cast<const unsigned long long*>(&g_dec[boff]);
            unsigned dw = nib_compact(Bv);
            unsigned uw = nib_compact(Bv >> 4);
            s_du[r * 8 + wq] = make_uint2(dw, uw);
            s_c[r * 8 + wq] = dw | uw;
        }
        __syncthreads();
        if (t == 0) {
            int jlo = jblo * 128 + 1;                  // smallest j inside the staged strips
            while (i >= ilo && j >= jlo) {
                int jj = j - 1;
                int r = i - ilo;
                int w = (jj >> 5) - jblo * 4;          // 0..7
                int bit = jj & 31;
                uint2 du = s_du[r * 8 + w];
                if ((du.x >> bit) & 1u) {
                    out[(size_t)(i - 1) * MM + jj] = 1.0f; --i; --j;
                } else if ((du.y >> bit) & 1u) {
                    --i;
                } else {
                    unsigned m = s_c[r * 8 + w] & ((bit == 0) ? 0u : ((1u << bit) - 1u));
                    for (;;) {
                        if (m) { int nb = 31 - __clz(m); j = (jblo * 4 + w) * 32 + nb + 1; break; }
                        if (w == 0) { j = jlo - 1; break; }
                        --w;
                        m = s_c[r * 8 + w];
                    }
                }
            }
            s_ij[0] = i; s_ij[1] = j;
        }
        __syncthreads();
        i = s_ij[0]; j = s_ij[1];
        __syncthreads();
    }
}

// ---------------- launch ----------------
extern "C" void kernel_launch(void* const* d_in, const int* in_sizes, int n_in,
                              void* d_out, int out_size) {
    (void)in_sizes; (void)n_in; (void)out_size;
    const float* text  = (const float*)d_in[2];
    const float* event = (const float*)d_in[3];
    float* out = (float*)d_out;

    // Probe removed (DP Tc measured in R9/R11). gemm_nt is launch #4 for ncu.
    init_state<<<256, 256>>>();
    normalize_rows<<<NN, 256>>>(text, 0);
    normalize_rows<<<MM, 256>>>(event, 1);
    gemm_nt<<<dim3(32, 32), 256>>>();
    for (int p = 0; p < 4; ++p) {
        int shift = 24 - 8 * p;
        hist_pass<<<2048, 256>>>(shift);
        select_pass<<<1, 256>>>(shift, p == 3 ? 1 : 0);
    }
    fill_zero4<<<2048, 256>>>((float4*)out, (size_t)NN * MM / 4);
    dp_kernel<<<NB, 32>>>(NN);
    traceback<<<1, 256>>>(out);
}

// round 14
// speedup vs baseline: 1.9125x; 1.0025x over previous
#include <cuda_runtime.h>
#include <cstdint>
#include <cstddef>

#define NN 4096
#define MM 4096
#define DD 1024
// k = int(4096*4096*0.3) = 5033164 ; ascending 0-based rank = 16777216 - k
#define RANK_ASC 11744052u
#define NB 32          // DP column chunks
#define CW 128         // columns per chunk
#define TBR 448        // traceback tile rows
#define NG (NN / 4)    // handoff groups (4 rows each)

// ---------------- static device scratch (no allocations allowed) ----------------
__device__ float    g_z[(size_t)NN * DD];
__device__ float    g_x[(size_t)MM * DD];
__device__ float    g_sim[(size_t)NN * MM];
// decision bytes, coalesced per block: g_dec[block*NN*32 + row*32 + lane]
__device__ unsigned char g_dec[(size_t)NN * 1024];
// boundary handoff, 4 rows per float4: g_bound2[b*NG + g] = D[4g+1..4g+4][b*CW]
__device__ float4   g_bound2[(size_t)NB * NG];
__device__ unsigned g_hist[256];
__device__ unsigned g_sel[2];   // [0]=prefix key, [1]=remaining rank
__device__ float    g_dropline;

// ---------------- helpers ----------------
__device__ __forceinline__ unsigned fkey(float f) {
    unsigned u = __float_as_uint(f);
    return (u & 0x80000000u) ? ~u : (u | 0x80000000u);
}
// volatile (strong) 128-bit handoff ops — single instruction each.
__device__ __forceinline__ float4 ldv4(const float4* p) {
    float4 v;
    asm volatile("ld.volatile.global.v4.f32 {%0,%1,%2,%3}, [%4];"
                 : "=f"(v.x), "=f"(v.y), "=f"(v.z), "=f"(v.w) : "l"(p));
    return v;
}
__device__ __forceinline__ void stv4(float4* p, float4 v) {
    asm volatile("st.volatile.global.v4.f32 [%0], {%1,%2,%3,%4};"
                 :: "l"(p), "f"(v.x), "f"(v.y), "f"(v.z), "f"(v.w));
}

// ---------------- init (must reset all mutable state every replay) ----------------
__global__ void init_state() {
    int idx = blockIdx.x * blockDim.x + threadIdx.x;
    if (idx < 256) g_hist[idx] = 0u;
    if (idx == 0) { g_sel[0] = 0u; g_sel[1] = RANK_ASC; }
    int total = NB * NG;
    float4 s; s.x = s.y = s.z = s.w = 1.0f;   // sentinel: real D values are <= 0
    for (int i = idx; i < total; i += gridDim.x * blockDim.x)
        g_bound2[i] = s;
}

__global__ void fill_zero4(float4* __restrict__ out, size_t n4) {
    size_t stride = (size_t)gridDim.x * blockDim.x;
    float4 z; z.x = z.y = z.z = z.w = 0.f;
    for (size_t i = blockIdx.x * (size_t)blockDim.x + threadIdx.x; i < n4; i += stride)
        out[i] = z;
}

// ---------------- row normalize ----------------
__global__ void normalize_rows(const float* __restrict__ in, int which) {
    int row = blockIdx.x;
    int t = threadIdx.x;                 // 256 threads
    const float* p = in + (size_t)row * DD;
    float s = 0.f;
#pragma unroll
    for (int k = 0; k < 4; k++) { float v = p[t + k * 256]; s = fmaf(v, v, s); }
    __shared__ float red[256];
    red[t] = s; __syncthreads();
    for (int o = 128; o > 0; o >>= 1) { if (t < o) red[t] += red[t + o]; __syncthreads(); }
    float nrm = sqrtf(red[0]);
    float* q = (which == 0 ? g_z : g_x) + (size_t)row * DD;
#pragma unroll
    for (int k = 0; k < 4; k++) q[t + k * 256] = p[t + k * 256] / nrm;
}

// ---------------- f32 NT GEMM: 256x128 block tile, 16x8 thread tile, BK=8 ----------------
// L1-traffic per FMA cut 25% vs 128x128/8x8 (a:32B + b:16B per 128 FMAs).
// Accumulation order per output element identical (ascending k, per-component
// IEEE fma) => bitwise-identical sim.
__global__ void __launch_bounds__(256, 1) gemm_nt() {
    __shared__ __align__(16) float As[2][8][260];
    __shared__ __align__(16) float Bs[2][8][132];
    int tid = threadIdx.x;
    int ty = tid >> 4;   // 0..15 -> 16 output rows each
    int tx = tid & 15;   // 0..15 -> 8 output cols each
    int bi = blockIdx.y * 256;
    int bj = blockIdx.x * 128;

    // acc2[rp][c] packs rows (ty*16+2rp, ty*16+2rp+1) at column tx*8+c
    unsigned long long acc2[8][8];
#pragma unroll
    for (int rp = 0; rp < 8; rp++)
#pragma unroll
        for (int c = 0; c < 8; c++) acc2[rp][c] = 0ull;

    // loader mapping: A row (bi+tid), k-chunks 0..3 and 4..7; B row (tid&127), chunk (tid>>7)*4
    int brow = tid & 127;
    int bk4 = (tid >> 7) * 4;

    {
        float4 va0 = *reinterpret_cast<const float4*>(&g_z[(size_t)(bi + tid) * DD + 0]);
        float4 va1 = *reinterpret_cast<const float4*>(&g_z[(size_t)(bi + tid) * DD + 4]);
        float4 vb0 = *reinterpret_cast<const float4*>(&g_x[(size_t)(bj + brow) * DD + bk4]);
        As[0][0][tid] = va0.x; As[0][1][tid] = va0.y;
        As[0][2][tid] = va0.z; As[0][3][tid] = va0.w;
        As[0][4][tid] = va1.x; As[0][5][tid] = va1.y;
        As[0][6][tid] = va1.z; As[0][7][tid] = va1.w;
        Bs[0][bk4 + 0][brow] = vb0.x; Bs[0][bk4 + 1][brow] = vb0.y;
        Bs[0][bk4 + 2][brow] = vb0.z; Bs[0][bk4 + 3][brow] = vb0.w;
    }
    __syncthreads();

    int s = 0;
    for (int k0 = 0; k0 < DD; k0 += 8, s ^= 1) {
        float4 va0, va1, vb0;
        bool more = (k0 + 8 < DD);
        if (more) {
            int kn = k0 + 8;
            va0 = *reinterpret_cast<const float4*>(&g_z[(size_t)(bi + tid) * DD + kn]);
            va1 = *reinterpret_cast<const float4*>(&g_z[(size_t)(bi + tid) * DD + kn + 4]);
            vb0 = *reinterpret_cast<const float4*>(&g_x[(size_t)(bj + brow) * DD + kn + bk4]);
        }
#pragma unroll
        for (int kk = 0; kk < 8; kk++) {
            const ulonglong2* ap2 = reinterpret_cast<const ulonglong2*>(&As[s][kk][ty * 16]);
            ulonglong2 aa = ap2[0], ab = ap2[1], ac = ap2[2], ad = ap2[3];
            unsigned long long a2[8];
            a2[0] = aa.x; a2[1] = aa.y; a2[2] = ab.x; a2[3] = ab.y;
            a2[4] = ac.x; a2[5] = ac.y; a2[6] = ad.x; a2[7] = ad.y;
            const float4* bp = reinterpret_cast<const float4*>(&Bs[s][kk][tx * 8]);
            float4 b0 = bp[0], b1 = bp[1];
            float bbv[8];
            bbv[0] = b0.x; bbv[1] = b0.y; bbv[2] = b0.z; bbv[3] = b0.w;
            bbv[4] = b1.x; bbv[5] = b1.y; bbv[6] = b1.z; bbv[7] = b1.w;
            unsigned long long b2[8];
#pragma unroll
            for (int c = 0; c < 8; c++)
                asm("mov.b64 %0, {%1, %1};" : "=l"(b2[c]) : "r"(__float_as_uint(bbv[c])));
#pragma unroll
            for (int c = 0; c < 8; c++)
#pragma unroll
                for (int rp = 0; rp < 8; rp++)
                    asm("fma.rn.f32x2 %0, %1, %2, %0;"
                        : "+l"(acc2[rp][c]) : "l"(a2[rp]), "l"(b2[c]));
        }
        __syncthreads();
        if (more) {
            int d = s ^ 1;
            As[d][0][tid] = va0.x; As[d][1][tid] = va0.y;
            As[d][2][tid] = va0.z; As[d][3][tid] = va0.w;
            As[d][4][tid] = va1.x; As[d][5][tid] = va1.y;
            As[d][6][tid] = va1.z; As[d][7][tid] = va1.w;
            Bs[d][bk4 + 0][brow] = vb0.x; Bs[d][bk4 + 1][brow] = vb0.y;
            Bs[d][bk4 + 2][brow] = vb0.z; Bs[d][bk4 + 3][brow] = vb0.w;
            __syncthreads();
        }
    }
#pragma unroll
    for (int rp = 0; rp < 8; rp++) {
        float lo[8], hi[8];
#pragma unroll
        for (int c = 0; c < 8; c++) {
            lo[c] = __uint_as_float((unsigned)(acc2[rp][c] & 0xffffffffull));
            hi[c] = __uint_as_float((unsigned)(acc2[rp][c] >> 32));
        }
        float* dst0 = &g_sim[(size_t)(bi + ty * 16 + 2 * rp) * MM + (bj + tx * 8)];
        float* dst1 = &g_sim[(size_t)(bi + ty * 16 + 2 * rp + 1) * MM + (bj + tx * 8)];
        float4 o;
        o.x = lo[0]; o.y = lo[1]; o.z = lo[2]; o.w = lo[3];
        *reinterpret_cast<float4*>(dst0) = o;
        o.x = lo[4]; o.y = lo[5]; o.z = lo[6]; o.w = lo[7];
        *reinterpret_cast<float4*>(dst0 + 4) = o;
        o.x = hi[0]; o.y = hi[1]; o.z = hi[2]; o.w = hi[3];
        *reinterpret_cast<float4*>(dst1) = o;
        o.x = hi[4]; o.y = hi[5]; o.z = hi[6]; o.w = hi[7];
        *reinterpret_cast<float4*>(dst1 + 4) = o;
    }
}

// ---------------- exact radix select (privatized per-warp hists) ----------------
__global__ void hist_pass(int shift) {
    __shared__ unsigned sh[8][256];
    int t = threadIdx.x;
    int wid = t >> 5;
    for (int k = t; k < 8 * 256; k += 256) ((unsigned*)sh)[k] = 0u;
    __syncthreads();
    unsigned prefix = g_sel[0];
    int above = shift + 8;
    size_t stride = (size_t)gridDim.x * blockDim.x;
    size_t total = (size_t)NN * MM;
    for (size_t i = blockIdx.x * (size_t)blockDim.x + threadIdx.x; i < total; i += stride) {
        unsigned u = fkey(g_sim[i]);
        bool ok = (above >= 32) || ((u >> above) == (prefix >> above));
        if (ok) atomicAdd(&sh[wid][(u >> shift) & 255u], 1u);
    }
    __syncthreads();
    unsigned tot = 0;
#pragma unroll
    for (int wq = 0; wq < 8; wq++) tot += sh[wq][t];
    if (tot) atomicAdd(&g_hist[t], tot);
}

__global__ void select_pass(int shift, int last) {
    __shared__ unsigned cnt[256];
    int t = threadIdx.x;
    cnt[t] = g_hist[t];
    g_hist[t] = 0u;   // reset for the next pass
    __syncthreads();
    if (t == 0) {
        unsigned rank = g_sel[1], cum = 0; int bin = 255;
        for (int b = 0; b < 256; b++) {
            unsigned c = cnt[b];
            if (cum + c > rank) { bin = b; break; }
            cum += c;
        }
        g_sel[0] |= ((unsigned)bin) << shift;
        g_sel[1] = rank - cum;
        if (last) {
            unsigned u = g_sel[0];
            unsigned bits = (u & 0x80000000u) ? (u & 0x7FFFFFFFu) : ~u;
            g_dropline = __uint_as_float(bits);
        }
    }
}

// ---------------- NW DP wavefront: volatile 4-row-batched handoff with early peek ----------------
__device__ __forceinline__ float dp_row(
    int lane, int i, float dropline, float4 simCur, float incoming,
    float& prev0, float& prev1, float& prev2, float& prev3,
    float& bcar, unsigned char* decp)
{
    float cc0 = dropline - simCur.x;
    float cc1 = dropline - simCur.y;
    float cc2 = dropline - simCur.z;
    float cc3 = dropline - simCur.w;

    float d0 = bcar + cc0;     // left neighbor = previous row's base (exact identity)
    float d1 = prev0 + cc1;
    float d2 = prev1 + cc2;
    float d3 = prev2 + cc3;
    float n0 = fminf(d0, prev0);
    float n1 = fminf(d1, prev1);
    float n2 = fminf(d2, prev2);
    float n3 = fminf(d3, prev3);
    float p0 = n0;
    float p1 = fminf(p0, n1);
    float p2 = fminf(p1, n2);
    float p3 = fminf(p2, n3);

    // warp inclusive min-scan of lane totals
    float S = p3;
#pragma unroll
    for (int o = 1; o < 32; o <<= 1) {
        float v = __shfl_up_sync(0xffffffffu, S, o);
        if (lane >= o) S = fminf(S, v);
    }
    float E = __shfl_up_sync(0xffffffffu, S, 1);   // exclusive prefix (lanes > 0)

    float nbase = (lane == 0) ? incoming : fminf(incoming, E);
    float D0 = fminf(nbase, p0);
    float D1 = fminf(nbase, p1);
    float D2 = fminf(nbase, p2);
    float D3 = fminf(nbase, p3);

    bool df0 = (D0 == d0); bool uf0 = (!df0) && (D0 == prev0);
    bool df1 = (D1 == d1); bool uf1 = (!df1) && (D1 == prev1);
    bool df2 = (D2 == d2); bool uf2 = (!df2) && (D2 == prev2);
    bool df3 = (D3 == d3); bool uf3 = (!df3) && (D3 == prev3);
    unsigned byte = (df0 ? 1u : 0u) | (df1 ? 2u : 0u) | (df2 ? 4u : 0u) | (df3 ? 8u : 0u)
                  | (uf0 ? 16u : 0u) | (uf1 ? 32u : 0u) | (uf2 ? 64u : 0u) | (uf3 ? 128u : 0u);
    decp[(size_t)(i - 1) * 32] = (unsigned char)byte;   // coalesced: 32B/warp/row

    prev0 = D0; prev1 = D1; prev2 = D2; prev3 = D3;
    bcar = nbase;
    return D3;
}

__device__ __forceinline__ bool inc_ready(float4 v) {
    return !(v.x > 0.5f || v.y > 0.5f || v.z > 0.5f || v.w > 0.5f);
}

__global__ void __launch_bounds__(32, 1) dp_kernel(int rows) {   // rows % 4 == 0
    const int b = blockIdx.x;
    const int lane = threadIdx.x;
    const int c0 = b * CW;
    const float dropline = g_dropline;
    const float* gsim = g_sim + c0 + 4 * lane;
    unsigned char* decp = g_dec + (size_t)b * NN * 32 + lane;

    float prev0 = 0.f, prev1 = 0.f, prev2 = 0.f, prev3 = 0.f;
    float bcar = 0.f;   // D[0][...] row is all zeros

    int ng = rows >> 2;
    // preload group 0's sim rows
    float4 s0 = *reinterpret_cast<const float4*>(gsim);
    float4 s1 = *reinterpret_cast<const float4*>(gsim + (size_t)1 * MM);
    float4 s2 = *reinterpret_cast<const float4*>(gsim + (size_t)2 * MM);
    float4 s3 = *reinterpret_cast<const float4*>(gsim + (size_t)3 * MM);

    // incoming for group 0
    float4 inc4; inc4.x = inc4.y = inc4.z = inc4.w = 0.f;
    if (b != 0) {
        const float4* pp = &g_bound2[(size_t)b * NG + 0];
        inc4 = ldv4(pp);
        while (!inc_ready(inc4)) inc4 = ldv4(pp);
    }

    for (int g = 0; g < ng; ++g) {
        float4 n0, n1, n2, n3;
        if (g + 1 < ng) {   // prefetch next group's sim rows
            const float* nb2 = gsim + (size_t)(4 * (g + 1)) * MM;
            n0 = *reinterpret_cast<const float4*>(nb2);
            n1 = *reinterpret_cast<const float4*>(nb2 + (size_t)1 * MM);
            n2 = *reinterpret_cast<const float4*>(nb2 + (size_t)2 * MM);
            n3 = *reinterpret_cast<const float4*>(nb2 + (size_t)3 * MM);
        }
        int i = 4 * g + 1;
        float4 out4;
        out4.x = dp_row(lane, i + 0, dropline, s0, inc4.x, prev0, prev1, prev2, prev3, bcar, decp);
        out4.y = dp_row(lane, i + 1, dropline, s1, inc4.y, prev0, prev1, prev2, prev3, bcar, decp);
        out4.z = dp_row(lane, i + 2, dropline, s2, inc4.z, prev0, prev1, prev2, prev3, bcar, decp);
        out4.w = dp_row(lane, i + 3, dropline, s3, inc4.w, prev0, prev1, prev2, prev3, bcar, decp);

        // EARLY PEEK for group g+1 BEFORE the publish store: LD precedes ST in
        // program order, so the store doesn't stall it; if the peek already has
        // data (steady state), the post-store spin is skipped entirely.
        float4 nxt; nxt.x = nxt.y = nxt.z = nxt.w = 0.f;
        const float4* pp = &g_bound2[(size_t)b * NG + (g + 1)];
        bool need = (b != 0) && (g + 1 < ng);
        if (need) nxt = ldv4(pp);

        if (lane == 31 && b < NB - 1)
            stv4(&g_bound2[(size_t)(b + 1) * NG + g], out4);

        if (need) { while (!inc_ready(nxt)) nxt = ldv4(pp); }
        inc4 = nxt;
        s0 = n0; s1 = n1; s2 = n2; s3 = n3;
    }
}

// ---------------- traceback: 448-row tiles, u64 nibble repack, left-run skipping ----------------
__device__ __forceinline__ unsigned nib_compact(unsigned long long x) {
    x &= 0x0F0F0F0F0F0F0F0Full;
    x = (x | (x >> 4))  & 0x00FF00FF00FF00FFull;
    x = (x | (x >> 8))  & 0x0000FFFF0000FFFFull;
    x = (x | (x >> 16));
    return (unsigned)x;
}

__global__ void traceback(float* __restrict__ out) {
    __shared__ uint2    s_du[TBR * 8];
    __shared__ unsigned s_c[TBR * 8];
    __shared__ int s_ij[2];
    int t = threadIdx.x;    // 256 threads
    int i = NN, j = MM;
    while (i > 0 && j > 0) {
        int ilo = (i - (TBR - 1) > 1) ? (i - (TBR - 1)) : 1;
        int jbhi = (j - 1) >> 7;                       // 128-col strip of current jj
        int jblo = (jbhi - 1 > 0) ? (jbhi - 1) : 0;    // stage 2 strips
        int rows = i - ilo + 1;
        for (int idx = t; idx < rows * 8; idx += 256) {
            int r = idx >> 3, wq = idx & 7;            // natural word 0..7 across 2 strips
            int strip = jblo + (wq >> 2), w4 = wq & 3;
            size_t boff = (size_t)strip * ((size_t)NN * 32)
                        + (size_t)(ilo - 1 + r) * 32 + (size_t)w4 * 8;
            unsigned long long Bv = *reinterpret_cast<const unsigned long long*>(&g_dec[boff]);
            unsigned dw = nib_compact(Bv);
            unsigned uw = nib_compact(Bv >> 4);
            s_du[r * 8 + wq] = make_uint2(dw, uw);
            s_c[r * 8 + wq] = dw | uw;
        }
        __syncthreads();
        if (t == 0) {
            int jlo = jblo * 128 + 1;                  // smallest j inside the staged strips
            while (i >= ilo && j >= jlo) {
                int jj = j - 1;
                int r = i - ilo;
                int w = (jj >> 5) - jblo * 4;          // 0..7
                int bit = jj & 31;
                uint2 du = s_du[r * 8 + w];
                if ((du.x >> bit) & 1u) {
                    out[(size_t)(i - 1) * MM + jj] = 1.0f; --i; --j;
                } else if ((du.y >> bit) & 1u) {
                    --i;
                } else {
                    unsigned m = s_c[r * 8 + w] & ((bit == 0) ? 0u : ((1u << bit) - 1u));
                    for (;;) {
                        if (m) { int nb = 31 - __clz(m); j = (jblo * 4 + w) * 32 + nb + 1; break; }
                        if (w == 0) { j = jlo - 1; break; }
                        --w;
                        m = s_c[r * 8 + w];
                    }
                }
            }
            s_ij[0] = i; s_ij[1] = j;
        }
        __syncthreads();
        i = s_ij[0]; j = s_ij[1];
        __syncthreads();
    }
}

// ---------------- launch ----------------
extern "C" void kernel_launch(void* const* d_in, const int* in_sizes, int n_in,
                              void* d_out, int out_size) {
    (void)in_sizes; (void)n_in; (void)out_size;
    const float* text  = (const float*)d_in[2];
    const float* event = (const float*)d_in[3];
    float* out = (float*)d_out;

    // gemm_nt is launch #4 for ncu (-s 5 -c 1 + 2 harness launches).
    init_state<<<256, 256>>>();
    normalize_rows<<<NN, 256>>>(text, 0);
    normalize_rows<<<MM, 256>>>(event, 1);
    gemm_nt<<<dim3(32, 16), 256>>>();
    for (int p = 0; p < 4; ++p) {
        int shift = 24 - 8 * p;
        hist_pass<<<2048, 256>>>(shift);
        select_pass<<<1, 256>>>(shift, p == 3 ? 1 : 0);
    }
    fill_zero4<<<2048, 256>>>((float4*)out, (size_t)NN * MM / 4);
    dp_kernel<<<NB, 32>>>(NN);
    traceback<<<1, 256>>>(out);
}